// round 2
// baseline (speedup 1.0000x reference)
#include <cuda_runtime.h>
#include <math.h>

// Problem constants (fixed by the dataset):
//   X: [16384, 1024] fp32
//   per layer i: wpn [2048, 2048], b [2048], a [1024, 9, 1]
//   scale: [1], out_bias: [1024]
//   out: [16384, 1024] fp32
#define NROWS 16384
#define INW   1024
#define OUTW  2048
#define NG    1024   // groups per layer output (= OUTW / ARITY)

// Ping-pong intermediate buffers (64 MB each) — static device globals, no allocation.
__device__ float g_buf0[(size_t)NROWS * NG];
__device__ float g_buf1[(size_t)NROWS * NG];

// Fused layer: Y[N, 1024] = act( (X*ls) @ (wpn_hi - wpn_lo) + b, a ) (+ out_bias if LAST)
// Tiling: 128x128 C-tile, BK=16, 256 threads, 8x8 microtile per thread.
template<int LAST>
__global__ __launch_bounds__(256, 2)
void layer_kernel(const float* __restrict__ X,
                  const float* __restrict__ wpn,
                  const float* __restrict__ bias,
                  const float* __restrict__ act,
                  const float* __restrict__ scale_p,
                  const float* __restrict__ out_bias,
                  float* __restrict__ Y)
{
    __shared__ float As[16][132];   // padded: transposed stores conflict-free-ish
    __shared__ float Bs[16][128];   // 512B row stride keeps float4 stores aligned

    const int tid     = threadIdx.x;
    const int rowBase = blockIdx.y * 128;
    const int colBase = blockIdx.x * 128;

    // layer_scale = (|scale| * SCALE_FACTOR)^(1/DEPTH), SCALE_FACTOR=1, DEPTH=3
    const float ls = cbrtf(fabsf(scale_p[0]));

    // A-load mapping: 128 rows x 16 k = 2048 floats / 256 thr = 8 floats (2x float4)
    const int aRow = tid >> 2;            // 0..63 (and +64)
    const int aK   = (tid & 3) << 2;      // 0,4,8,12
    // B-load mapping: 16 k x 128 n; one float4 per (k,thread), 2 passes over k
    const int bK   = tid >> 5;            // 0..7 (and +8)
    const int bN   = (tid & 31) << 2;     // 0..124

    const int ty = tid >> 4;              // 0..15 -> row microtile
    const int tx = tid & 15;              // 0..15 -> col microtile

    float acc[8][8];
    #pragma unroll
    for (int i = 0; i < 8; i++)
        #pragma unroll
        for (int j = 0; j < 8; j++) acc[i][j] = 0.f;

    for (int k0 = 0; k0 < INW; k0 += 16) {
        // ---- load A tile (scaled, transposed into As[k][m]) ----
        {
            const float4 v0 = *(const float4*)(X + (size_t)(rowBase + aRow)      * INW + k0 + aK);
            const float4 v1 = *(const float4*)(X + (size_t)(rowBase + aRow + 64) * INW + k0 + aK);
            As[aK+0][aRow]    = v0.x * ls;
            As[aK+1][aRow]    = v0.y * ls;
            As[aK+2][aRow]    = v0.z * ls;
            As[aK+3][aRow]    = v0.w * ls;
            As[aK+0][aRow+64] = v1.x * ls;
            As[aK+1][aRow+64] = v1.y * ls;
            As[aK+2][aRow+64] = v1.z * ls;
            As[aK+3][aRow+64] = v1.w * ls;
        }
        // ---- load B tile: raw_w = wpn[k, :] - wpn[k+1024, :] ----
        #pragma unroll
        for (int pass = 0; pass < 2; pass++) {
            const int k = bK + pass * 8;
            const float* p = wpn + (size_t)(k0 + k) * OUTW + colBase + bN;
            const float4 h = *(const float4*)p;
            const float4 l = *(const float4*)(p + (size_t)INW * OUTW);
            float4 r;
            r.x = h.x - l.x; r.y = h.y - l.y; r.z = h.z - l.z; r.w = h.w - l.w;
            *(float4*)&Bs[k][bN] = r;
        }
        __syncthreads();

        // ---- 8x8 microtile FMA ----
        #pragma unroll
        for (int kk = 0; kk < 16; kk++) {
            float ar[8], br[8];
            #pragma unroll
            for (int i = 0; i < 8; i++) ar[i] = As[kk][ty * 8 + i];
            #pragma unroll
            for (int j = 0; j < 8; j++) br[j] = Bs[kk][tx * 8 + j];
            #pragma unroll
            for (int i = 0; i < 8; i++)
                #pragma unroll
                for (int j = 0; j < 8; j++)
                    acc[i][j] = fmaf(ar[i], br[j], acc[i][j]);
        }
        __syncthreads();
    }

    // ---- fused epilogue: bias + multilinear grid activation (ARITY=2) ----
    // Thread's 8 columns are contiguous & even-aligned -> 4 complete (x0,x1) pairs,
    // producing 4 consecutive output groups -> one float4 store per row.
    #pragma unroll
    for (int r = 0; r < 8; r++) {
        const int row = rowBase + ty * 8 + r;
        float o4[4];
        #pragma unroll
        for (int p = 0; p < 4; p++) {
            const int c0 = colBase + tx * 8 + 2 * p;
            float x0 = acc[r][2*p]     + bias[c0];
            float x1 = acc[r][2*p + 1] + bias[c0 + 1];
            const int g = c0 >> 1;
            // clamp to [-1, 1]
            x0 = fminf(fmaxf(x0, -1.f), 1.f);
            x1 = fminf(fmaxf(x1, -1.f), 1.f);
            // lower grid coord in {-1, 0}; cell vertex base id
            const float lo0 = (x0 < 0.f) ? -1.f : 0.f;
            const float lo1 = (x1 < 0.f) ? -1.f : 0.f;
            const float f0 = x0 - lo0;      // frac in [0,1]
            const float f1 = x1 - lo1;
            const int base = ((x0 < 0.f) ? 0 : 1) + 3 * ((x1 < 0.f) ? 0 : 1);
            const float* av = act + g * 9;
            const float v00 = __ldg(av + base);
            const float v10 = __ldg(av + base + 1);
            const float v01 = __ldg(av + base + 3);
            const float v11 = __ldg(av + base + 4);
            float o = (1.f - f0) * ((1.f - f1) * v00 + f1 * v01)
                    +        f0  * ((1.f - f1) * v10 + f1 * v11);
            if (LAST) o += out_bias[g];
            o4[p] = o;
        }
        const int gBase = (colBase >> 1) + tx * 4;
        float4 ov;
        ov.x = o4[0]; ov.y = o4[1]; ov.z = o4[2]; ov.w = o4[3];
        *(float4*)(Y + (size_t)row * NG + gBase) = ov;
    }
}

extern "C" void kernel_launch(void* const* d_in, const int* in_sizes, int n_in,
                              void* d_out, int out_size)
{
    (void)in_sizes; (void)n_in; (void)out_size;
    const float* X     = (const float*)d_in[0];
    const float* w0    = (const float*)d_in[1];
    const float* b0    = (const float*)d_in[2];
    const float* a0    = (const float*)d_in[3];
    const float* w1    = (const float*)d_in[4];
    const float* b1    = (const float*)d_in[5];
    const float* a1    = (const float*)d_in[6];
    const float* w2    = (const float*)d_in[7];
    const float* b2    = (const float*)d_in[8];
    const float* a2    = (const float*)d_in[9];
    const float* scale = (const float*)d_in[10];
    const float* outb  = (const float*)d_in[11];
    float* out = (float*)d_out;

    float *buf0 = nullptr, *buf1 = nullptr;
    cudaGetSymbolAddress((void**)&buf0, g_buf0);
    cudaGetSymbolAddress((void**)&buf1, g_buf1);

    dim3 grid(OUTW / 128, NROWS / 128);   // (16, 128)
    dim3 block(256);

    layer_kernel<0><<<grid, block>>>(X,    w0, b0, a0, scale, nullptr, buf0);
    layer_kernel<0><<<grid, block>>>(buf0, w1, b1, a1, scale, nullptr, buf1);
    layer_kernel<1><<<grid, block>>>(buf1, w2, b2, a2, scale, outb,    out);
}

// round 5
// speedup vs baseline: 2.3644x; 2.3644x over previous
#include <cuda_runtime.h>
#include <cuda_bf16.h>
#include <math.h>
#include <stdint.h>

// Problem constants:
//   X: [16384, 1024] fp32; per layer: wpn [2048,2048], b [2048], a [1024,9,1]
//   scale [1], out_bias [1024]; out [16384,1024] fp32
#define NROWS 16384
#define INW   1024
#define OUTW  2048
#define NG    1024

#define BM 128
#define BN 128
#define BK 64
#define NCHUNK (INW / BK)      // 16

// SMEM stage layout: 4 tiles of [128 rows][64 bf16 = 128B] = 16KB each
#define OFF_AH 0
#define OFF_AL 16384
#define OFF_BH 32768
#define OFF_BL 49152
#define STAGE  65536
#define NSTAGE 3
#define SMEM_TOTAL (NSTAGE * STAGE)   // 196608

// -------- static device buffers (no allocation) --------
__device__ __nv_bfloat16 g_Ahi0[(size_t)NROWS * INW];
__device__ __nv_bfloat16 g_Alo0[(size_t)NROWS * INW];
__device__ __nv_bfloat16 g_Ahi1[(size_t)NROWS * INW];
__device__ __nv_bfloat16 g_Alo1[(size_t)NROWS * INW];
__device__ __nv_bfloat16 g_Bhi[3][(size_t)OUTW * INW];
__device__ __nv_bfloat16 g_Blo[3][(size_t)OUTW * INW];

// -------- PTX helpers (all legal on compute_100) --------
__device__ __forceinline__ uint32_t smem_u32(const void* p) {
    uint32_t a;
    asm("{ .reg .u64 t; cvta.to.shared.u64 t, %1; cvt.u32.u64 %0, t; }" : "=r"(a) : "l"(p));
    return a;
}
#define CP_ASYNC16(dst, src) \
    asm volatile("cp.async.cg.shared.global [%0], [%1], 16;" :: "r"(dst), "l"(src))
#define CP_COMMIT() asm volatile("cp.async.commit_group;" ::: "memory")
#define CP_WAIT2()  asm volatile("cp.async.wait_group 2;" ::: "memory")
#define CP_WAIT1()  asm volatile("cp.async.wait_group 1;" ::: "memory")
#define CP_WAIT0()  asm volatile("cp.async.wait_group 0;" ::: "memory")

#define LDSM4(r0, r1, r2, r3, addr) \
    asm volatile("ldmatrix.sync.aligned.m8n8.x4.shared.b16 {%0,%1,%2,%3}, [%4];" \
                 : "=r"(r0), "=r"(r1), "=r"(r2), "=r"(r3) : "r"(addr))

#define MMA_BF16(d, a, b0, b1) \
    asm volatile("mma.sync.aligned.m16n8k16.row.col.f32.bf16.bf16.f32 " \
                 "{%0,%1,%2,%3},{%4,%5,%6,%7},{%8,%9},{%0,%1,%2,%3};" \
                 : "+f"((d)[0]), "+f"((d)[1]), "+f"((d)[2]), "+f"((d)[3]) \
                 : "r"((a)[0]), "r"((a)[1]), "r"((a)[2]), "r"((a)[3]), "r"(b0), "r"(b1))

// -------- prep kernels --------
__global__ void prep_x(const float* __restrict__ X, const float* __restrict__ scale_p,
                       __nv_bfloat16* __restrict__ Ahi, __nv_bfloat16* __restrict__ Alo)
{
    const float ls = cbrtf(fabsf(scale_p[0]));
    size_t i = ((size_t)blockIdx.x * 256 + threadIdx.x) * 4;
    float4 v = *(const float4*)(X + i);
    float w[4] = { v.x * ls, v.y * ls, v.z * ls, v.w * ls };
    uint32_t hp[2], lp[2];
    #pragma unroll
    for (int j = 0; j < 4; j++) {
        __nv_bfloat16 h = __float2bfloat16(w[j]);
        float rem = w[j] - __bfloat162float(h);
        __nv_bfloat16 l = __float2bfloat16(rem);
        uint32_t hb = (uint32_t)__bfloat16_as_ushort(h);
        uint32_t lb = (uint32_t)__bfloat16_as_ushort(l);
        if (j & 1) { hp[j >> 1] |= hb << 16; lp[j >> 1] |= lb << 16; }
        else       { hp[j >> 1]  = hb;       lp[j >> 1]  = lb; }
    }
    *(uint2*)(Ahi + i) = make_uint2(hp[0], hp[1]);
    *(uint2*)(Alo + i) = make_uint2(lp[0], lp[1]);
}

// raw_w[k][n] = wpn[k][n] - wpn[k+1024][n]; output transposed Bt[n][k] as bf16 hi/lo.
__global__ void prep_w(const float* __restrict__ wpn,
                       __nv_bfloat16* __restrict__ Bhi, __nv_bfloat16* __restrict__ Blo)
{
    __shared__ float t[32][33];
    const int k0 = blockIdx.x * 32, n0 = blockIdx.y * 32;
    const int tx = threadIdx.x, ty = threadIdx.y;   // (32, 8)
    #pragma unroll
    for (int i = 0; i < 32; i += 8) {
        int k = k0 + ty + i, n = n0 + tx;
        t[ty + i][tx] = wpn[(size_t)k * OUTW + n] - wpn[(size_t)(k + INW) * OUTW + n];
    }
    __syncthreads();
    #pragma unroll
    for (int i = 0; i < 32; i += 8) {
        int n = n0 + ty + i, k = k0 + tx;
        float v = t[tx][ty + i];
        __nv_bfloat16 h = __float2bfloat16(v);
        float rem = v - __bfloat162float(h);
        Bhi[(size_t)n * INW + k] = h;
        Blo[(size_t)n * INW + k] = __float2bfloat16(rem);
    }
}

// -------- fused GEMM(bf16x3, mma.sync) + activation --------
__device__ __forceinline__ void compute_stage(
    uint32_t stA_hi, uint32_t stA_lo, uint32_t stB_hi, uint32_t stB_lo,
    int lane, int warp_m, int warp_n, float acc[4][4][4])
{
    const uint32_t swx  = (uint32_t)(lane & 7) * 16;
    const uint32_t rsel = (uint32_t)(lane & 15);
    const uint32_t csel = (uint32_t)(lane >> 4) * 16;
    #pragma unroll
    for (int ks = 0; ks < 4; ks++) {
        const uint32_t col = ((uint32_t)ks * 32 + csel) ^ swx;
        uint32_t ah[4][4], al[4][4], bh[2][4], bl[2][4];
        #pragma unroll
        for (int mb = 0; mb < 4; mb++) {
            uint32_t ro = (uint32_t)(warp_m + mb * 16 + rsel) * 128 + col;
            LDSM4(ah[mb][0], ah[mb][1], ah[mb][2], ah[mb][3], stA_hi + ro);
            LDSM4(al[mb][0], al[mb][1], al[mb][2], al[mb][3], stA_lo + ro);
        }
        #pragma unroll
        for (int pb = 0; pb < 2; pb++) {
            uint32_t ro = (uint32_t)(warp_n + pb * 16 + rsel) * 128 + col;
            LDSM4(bh[pb][0], bh[pb][1], bh[pb][2], bh[pb][3], stB_hi + ro);
            LDSM4(bl[pb][0], bl[pb][1], bl[pb][2], bl[pb][3], stB_lo + ro);
        }
        #pragma unroll
        for (int mb = 0; mb < 4; mb++)
            #pragma unroll
            for (int nb = 0; nb < 4; nb++) {
                const int pb = nb >> 1, s = nb & 1;
                MMA_BF16(acc[mb][nb], ah[mb], bh[pb][s], bh[pb][s + 2]);
                MMA_BF16(acc[mb][nb], ah[mb], bl[pb][s], bl[pb][s + 2]);
                MMA_BF16(acc[mb][nb], al[mb], bh[pb][s], bh[pb][s + 2]);
            }
    }
}

__device__ __forceinline__ float act_eval(float x0, float x1, const float* __restrict__ av)
{
    x0 = fminf(fmaxf(x0, -1.f), 1.f);
    x1 = fminf(fmaxf(x1, -1.f), 1.f);
    const float lo0 = (x0 < 0.f) ? -1.f : 0.f;
    const float lo1 = (x1 < 0.f) ? -1.f : 0.f;
    const float f0 = x0 - lo0;
    const float f1 = x1 - lo1;
    const int base = ((x0 < 0.f) ? 0 : 1) + 3 * ((x1 < 0.f) ? 0 : 1);
    const float v00 = __ldg(av + base);
    const float v10 = __ldg(av + base + 1);
    const float v01 = __ldg(av + base + 3);
    const float v11 = __ldg(av + base + 4);
    return (1.f - f0) * ((1.f - f1) * v00 + f1 * v01)
         +        f0  * ((1.f - f1) * v10 + f1 * v11);
}

template<int LAST>
__global__ void __launch_bounds__(256, 1)
gemm_act(const __nv_bfloat16* __restrict__ Ahi, const __nv_bfloat16* __restrict__ Alo,
         const __nv_bfloat16* __restrict__ Bhi, const __nv_bfloat16* __restrict__ Blo,
         const float* __restrict__ bias, const float* __restrict__ act,
         const float* __restrict__ scale_p, const float* __restrict__ out_bias,
         __nv_bfloat16* __restrict__ Yhi, __nv_bfloat16* __restrict__ Ylo,
         float* __restrict__ Yout)
{
    extern __shared__ __align__(1024) char smem[];
    const uint32_t sb = smem_u32(smem);
    const int tid  = threadIdx.x;
    const int wid  = tid >> 5;
    const int lane = tid & 31;
    const int rowBase = blockIdx.y * BM;
    const int nBase   = blockIdx.x * BN;
    const int warp_m = (wid & 1) * 64;
    const int warp_n = (wid >> 1) * 32;

    // ---- loader mapping: thread -> 4 rows x 1 chunk per tile ----
    const int r0   = tid >> 3;            // 0..31
    const int cseg = (tid & 7) * 16;      // byte seg within 128B row
    uint32_t swOff[4];
    #pragma unroll
    for (int i = 0; i < 4; i++)
        swOff[i] = (uint32_t)(r0 + 32 * i) * 128 + ((uint32_t)cseg ^ ((uint32_t)(r0 & 7) * 16));

    const char* gAh = (const char*)(Ahi + (size_t)(rowBase + r0) * INW) + cseg;
    const char* gAl = (const char*)(Alo + (size_t)(rowBase + r0) * INW) + cseg;
    const char* gBh = (const char*)(Bhi + (size_t)(nBase  + r0) * INW) + cseg;
    const char* gBl = (const char*)(Blo + (size_t)(nBase  + r0) * INW) + cseg;
    const size_t RSTRIDE = (size_t)32 * INW * 2;   // 32 rows

    float acc[4][4][4];
    #pragma unroll
    for (int a = 0; a < 4; a++)
        #pragma unroll
        for (int b = 0; b < 4; b++)
            #pragma unroll
            for (int q = 0; q < 4; q++) acc[a][b][q] = 0.f;

    // prologue: stages 0 and 1
    #pragma unroll
    for (int p = 0; p < 2; p++) {
        const uint32_t st = sb + p * STAGE;
        const size_t go = (size_t)p * 128;   // BK*2 bytes along k
        #pragma unroll
        for (int i = 0; i < 4; i++) {
            CP_ASYNC16(st + OFF_AH + swOff[i], gAh + go + i * RSTRIDE);
            CP_ASYNC16(st + OFF_AL + swOff[i], gAl + go + i * RSTRIDE);
            CP_ASYNC16(st + OFF_BH + swOff[i], gBh + go + i * RSTRIDE);
            CP_ASYNC16(st + OFF_BL + swOff[i], gBl + go + i * RSTRIDE);
        }
        CP_COMMIT();
    }

    for (int c = 0; c < NCHUNK; c++) {
        if (c + 2 < NCHUNK) {
            const uint32_t st = sb + ((c + 2) % NSTAGE) * STAGE;
            const size_t go = (size_t)(c + 2) * 128;
            #pragma unroll
            for (int i = 0; i < 4; i++) {
                CP_ASYNC16(st + OFF_AH + swOff[i], gAh + go + i * RSTRIDE);
                CP_ASYNC16(st + OFF_AL + swOff[i], gAl + go + i * RSTRIDE);
                CP_ASYNC16(st + OFF_BH + swOff[i], gBh + go + i * RSTRIDE);
                CP_ASYNC16(st + OFF_BL + swOff[i], gBl + go + i * RSTRIDE);
            }
            CP_COMMIT();
            CP_WAIT2();
        } else if (c + 1 < NCHUNK) {
            CP_WAIT1();
        } else {
            CP_WAIT0();
        }
        __syncthreads();
        const uint32_t st = sb + (c % NSTAGE) * STAGE;
        compute_stage(st + OFF_AH, st + OFF_AL, st + OFF_BH, st + OFF_BL,
                      lane, warp_m, warp_n, acc);
        __syncthreads();
    }

    // ---- epilogue: bias + grid activation ----
    const float ls = cbrtf(fabsf(scale_p[0]));
    const int gWarp = ((nBase + warp_n) >> 1);

    #pragma unroll
    for (int mb = 0; mb < 4; mb++) {
        const int rlo = rowBase + warp_m + mb * 16 + (lane >> 2);
        #pragma unroll
        for (int nb = 0; nb < 4; nb++) {
            const int g  = gWarp + nb * 4 + (lane & 3);
            const int c0 = 2 * g;
            const float b0v = bias[c0], b1v = bias[c0 + 1];
            const float* av = act + (size_t)g * 9;
            const float* d = acc[mb][nb];
            const float oLo = act_eval(d[0] + b0v, d[1] + b1v, av);
            const float oHi = act_eval(d[2] + b0v, d[3] + b1v, av);
            if (LAST) {
                const float ob = out_bias[g];
                Yout[(size_t)rlo * NG + g]       = oLo + ob;
                Yout[(size_t)(rlo + 8) * NG + g] = oHi + ob;
            } else {
                const float wLo = oLo * ls, wHi = oHi * ls;
                const __nv_bfloat16 hL = __float2bfloat16(wLo);
                const __nv_bfloat16 hH = __float2bfloat16(wHi);
                Yhi[(size_t)rlo * NG + g]       = hL;
                Yhi[(size_t)(rlo + 8) * NG + g] = hH;
                Ylo[(size_t)rlo * NG + g]       = __float2bfloat16(wLo - __bfloat162float(hL));
                Ylo[(size_t)(rlo + 8) * NG + g] = __float2bfloat16(wHi - __bfloat162float(hH));
            }
        }
    }
}

extern "C" void kernel_launch(void* const* d_in, const int* in_sizes, int n_in,
                              void* d_out, int out_size)
{
    (void)in_sizes; (void)n_in; (void)out_size;
    const float* X     = (const float*)d_in[0];
    const float* w0    = (const float*)d_in[1];
    const float* b0    = (const float*)d_in[2];
    const float* a0    = (const float*)d_in[3];
    const float* w1    = (const float*)d_in[4];
    const float* b1    = (const float*)d_in[5];
    const float* a1    = (const float*)d_in[6];
    const float* w2    = (const float*)d_in[7];
    const float* b2    = (const float*)d_in[8];
    const float* a2    = (const float*)d_in[9];
    const float* scale = (const float*)d_in[10];
    const float* outb  = (const float*)d_in[11];
    float* out = (float*)d_out;

    __nv_bfloat16 *Ah0, *Al0, *Ah1, *Al1, *Bh, *Bl;
    cudaGetSymbolAddress((void**)&Ah0, g_Ahi0);
    cudaGetSymbolAddress((void**)&Al0, g_Alo0);
    cudaGetSymbolAddress((void**)&Ah1, g_Ahi1);
    cudaGetSymbolAddress((void**)&Al1, g_Alo1);
    cudaGetSymbolAddress((void**)&Bh,  g_Bhi);
    cudaGetSymbolAddress((void**)&Bl,  g_Blo);
    const size_t WSTRIDE = (size_t)OUTW * INW;

    cudaFuncSetAttribute(gemm_act<0>, cudaFuncAttributeMaxDynamicSharedMemorySize, SMEM_TOTAL);
    cudaFuncSetAttribute(gemm_act<1>, cudaFuncAttributeMaxDynamicSharedMemorySize, SMEM_TOTAL);

    prep_x<<<(NROWS * INW) / (256 * 4), 256>>>(X, scale, Ah0, Al0);
    dim3 wgrid(INW / 32, OUTW / 32), wblk(32, 8);
    prep_w<<<wgrid, wblk>>>(w0, Bh + 0 * WSTRIDE, Bl + 0 * WSTRIDE);
    prep_w<<<wgrid, wblk>>>(w1, Bh + 1 * WSTRIDE, Bl + 1 * WSTRIDE);
    prep_w<<<wgrid, wblk>>>(w2, Bh + 2 * WSTRIDE, Bl + 2 * WSTRIDE);

    dim3 ggrid(OUTW / BN, NROWS / BM);   // (16, 128)
    gemm_act<0><<<ggrid, 256, SMEM_TOTAL>>>(Ah0, Al0, Bh + 0 * WSTRIDE, Bl + 0 * WSTRIDE,
                                            b0, a0, scale, nullptr, Ah1, Al1, nullptr);
    gemm_act<0><<<ggrid, 256, SMEM_TOTAL>>>(Ah1, Al1, Bh + 1 * WSTRIDE, Bl + 1 * WSTRIDE,
                                            b1, a1, scale, nullptr, Ah0, Al0, nullptr);
    gemm_act<1><<<ggrid, 256, SMEM_TOTAL>>>(Ah0, Al0, Bh + 2 * WSTRIDE, Bl + 2 * WSTRIDE,
                                            b2, a2, scale, outb, nullptr, nullptr, out);
}

// round 6
// speedup vs baseline: 3.4821x; 1.4727x over previous
#include <cuda_runtime.h>
#include <cuda_fp16.h>
#include <math.h>
#include <stdint.h>

// Problem constants:
//   X: [16384, 1024] fp32; per layer: wpn [2048,2048], b [2048], a [1024,9,1]
//   scale [1], out_bias [1024]; out [16384,1024] fp32
#define NROWS 16384
#define INW   1024
#define OUTW  2048
#define NG    1024

#define BM 128
#define BN 128
#define BK 64
#define NCHUNK (INW / BK)      // 16

// SMEM stage: A (128x64 fp16 = 16KB) + Bhi (16KB) + Blo (16KB)
#define OFF_A  0
#define OFF_BH 16384
#define OFF_BL 32768
#define STAGE  49152
#define NSTAGE 4
#define SMEM_TOTAL (NSTAGE * STAGE)   // 196608

// -------- static device buffers (no allocation) --------
__device__ __half g_A0[(size_t)NROWS * INW];
__device__ __half g_A1[(size_t)NROWS * INW];
__device__ __half g_Bhi[3][(size_t)OUTW * INW];
__device__ __half g_Blo[3][(size_t)OUTW * INW];

// -------- PTX helpers (legal on compute_100) --------
__device__ __forceinline__ uint32_t smem_u32(const void* p) {
    uint32_t a;
    asm("{ .reg .u64 t; cvta.to.shared.u64 t, %1; cvt.u32.u64 %0, t; }" : "=r"(a) : "l"(p));
    return a;
}
#define CP_ASYNC16(dst, src) \
    asm volatile("cp.async.cg.shared.global [%0], [%1], 16;" :: "r"(dst), "l"(src))
#define CP_COMMIT() asm volatile("cp.async.commit_group;" ::: "memory")
#define CP_WAIT2()  asm volatile("cp.async.wait_group 2;" ::: "memory")
#define CP_WAIT1()  asm volatile("cp.async.wait_group 1;" ::: "memory")
#define CP_WAIT0()  asm volatile("cp.async.wait_group 0;" ::: "memory")

#define LDSM4(r0, r1, r2, r3, addr) \
    asm volatile("ldmatrix.sync.aligned.m8n8.x4.shared.b16 {%0,%1,%2,%3}, [%4];" \
                 : "=r"(r0), "=r"(r1), "=r"(r2), "=r"(r3) : "r"(addr))

#define MMA_F16(d, a, b0, b1) \
    asm volatile("mma.sync.aligned.m16n8k16.row.col.f32.f16.f16.f32 " \
                 "{%0,%1,%2,%3},{%4,%5,%6,%7},{%8,%9},{%0,%1,%2,%3};" \
                 : "+f"((d)[0]), "+f"((d)[1]), "+f"((d)[2]), "+f"((d)[3]) \
                 : "r"((a)[0]), "r"((a)[1]), "r"((a)[2]), "r"((a)[3]), "r"(b0), "r"(b1))

// -------- prep kernels --------
__global__ void prep_x(const float* __restrict__ X, const float* __restrict__ scale_p,
                       __half* __restrict__ A)
{
    const float ls = cbrtf(fabsf(scale_p[0]));
    size_t i = ((size_t)blockIdx.x * 256 + threadIdx.x) * 4;
    float4 v = *(const float4*)(X + i);
    uint32_t p0, p1;
    __half2 h01 = __floats2half2_rn(v.x * ls, v.y * ls);
    __half2 h23 = __floats2half2_rn(v.z * ls, v.w * ls);
    p0 = *(uint32_t*)&h01;
    p1 = *(uint32_t*)&h23;
    *(uint2*)(A + i) = make_uint2(p0, p1);
}

// raw_w[k][n] = wpn[k][n] - wpn[k+1024][n]; transposed Bt[n][k] as fp16 hi + residual lo.
__global__ void prep_w(const float* __restrict__ wpn,
                       __half* __restrict__ Bhi, __half* __restrict__ Blo)
{
    __shared__ float t[32][33];
    const int k0 = blockIdx.x * 32, n0 = blockIdx.y * 32;
    const int tx = threadIdx.x, ty = threadIdx.y;   // (32, 8)
    #pragma unroll
    for (int i = 0; i < 32; i += 8) {
        int k = k0 + ty + i, n = n0 + tx;
        t[ty + i][tx] = wpn[(size_t)k * OUTW + n] - wpn[(size_t)(k + INW) * OUTW + n];
    }
    __syncthreads();
    #pragma unroll
    for (int i = 0; i < 32; i += 8) {
        int n = n0 + ty + i, k = k0 + tx;
        float v = t[tx][ty + i];
        __half h = __float2half_rn(v);
        Bhi[(size_t)n * INW + k] = h;
        Blo[(size_t)n * INW + k] = __float2half_rn(v - __half2float(h));
    }
}

// -------- fused GEMM(fp16 2-pass, mma.sync) + activation --------
__device__ __forceinline__ void compute_stage(
    uint32_t stA, uint32_t stB_hi, uint32_t stB_lo,
    int lane, int warp_m, int warp_n, float acc[4][4][4])
{
    const uint32_t swx  = (uint32_t)(lane & 7) * 16;
    const uint32_t rsel = (uint32_t)(lane & 15);
    const uint32_t csel = (uint32_t)(lane >> 4) * 16;
    #pragma unroll
    for (int ks = 0; ks < 4; ks++) {
        const uint32_t col = ((uint32_t)ks * 32 + csel) ^ swx;
        uint32_t ah[4][4], bh[2][4], bl[2][4];
        #pragma unroll
        for (int mb = 0; mb < 4; mb++) {
            uint32_t ro = (uint32_t)(warp_m + mb * 16 + rsel) * 128 + col;
            LDSM4(ah[mb][0], ah[mb][1], ah[mb][2], ah[mb][3], stA + ro);
        }
        #pragma unroll
        for (int pb = 0; pb < 2; pb++) {
            uint32_t ro = (uint32_t)(warp_n + pb * 16 + rsel) * 128 + col;
            LDSM4(bh[pb][0], bh[pb][1], bh[pb][2], bh[pb][3], stB_hi + ro);
            LDSM4(bl[pb][0], bl[pb][1], bl[pb][2], bl[pb][3], stB_lo + ro);
        }
        #pragma unroll
        for (int mb = 0; mb < 4; mb++)
            #pragma unroll
            for (int nb = 0; nb < 4; nb++) {
                const int pb = nb >> 1, s = nb & 1;
                MMA_F16(acc[mb][nb], ah[mb], bh[pb][s], bh[pb][s + 2]);
                MMA_F16(acc[mb][nb], ah[mb], bl[pb][s], bl[pb][s + 2]);
            }
    }
}

__device__ __forceinline__ float act_eval(float x0, float x1, const float* __restrict__ av)
{
    x0 = fminf(fmaxf(x0, -1.f), 1.f);
    x1 = fminf(fmaxf(x1, -1.f), 1.f);
    const float lo0 = (x0 < 0.f) ? -1.f : 0.f;
    const float lo1 = (x1 < 0.f) ? -1.f : 0.f;
    const float f0 = x0 - lo0;
    const float f1 = x1 - lo1;
    const int base = ((x0 < 0.f) ? 0 : 1) + 3 * ((x1 < 0.f) ? 0 : 1);
    const float v00 = __ldg(av + base);
    const float v10 = __ldg(av + base + 1);
    const float v01 = __ldg(av + base + 3);
    const float v11 = __ldg(av + base + 4);
    return (1.f - f0) * ((1.f - f1) * v00 + f1 * v01)
         +        f0  * ((1.f - f1) * v10 + f1 * v11);
}

template<int LAST>
__global__ void __launch_bounds__(256, 1)
gemm_act(const __half* __restrict__ A,
         const __half* __restrict__ Bhi, const __half* __restrict__ Blo,
         const float* __restrict__ bias, const float* __restrict__ act,
         const float* __restrict__ scale_p, const float* __restrict__ out_bias,
         __half* __restrict__ Ynext, float* __restrict__ Yout)
{
    extern __shared__ __align__(1024) char smem[];
    const uint32_t sb = smem_u32(smem);
    const int tid  = threadIdx.x;
    const int wid  = tid >> 5;
    const int lane = tid & 31;
    const int rowBase = blockIdx.y * BM;
    const int nBase   = blockIdx.x * BN;
    const int warp_m = (wid & 1) * 64;
    const int warp_n = (wid >> 1) * 32;

    // ---- loader mapping: thread -> 4 rows x 1 seg per tile ----
    const int r0   = tid >> 3;            // 0..31
    const int cseg = (tid & 7) * 16;      // byte seg within 128B row
    uint32_t swOff[4];
    #pragma unroll
    for (int i = 0; i < 4; i++)
        swOff[i] = (uint32_t)(r0 + 32 * i) * 128 + ((uint32_t)cseg ^ ((uint32_t)(r0 & 7) * 16));

    const char* gA  = (const char*)(A   + (size_t)(rowBase + r0) * INW) + cseg;
    const char* gBh = (const char*)(Bhi + (size_t)(nBase  + r0) * INW) + cseg;
    const char* gBl = (const char*)(Blo + (size_t)(nBase  + r0) * INW) + cseg;
    const size_t RSTRIDE = (size_t)32 * INW * 2;   // 32 rows

    float acc[4][4][4];
    #pragma unroll
    for (int a = 0; a < 4; a++)
        #pragma unroll
        for (int b = 0; b < 4; b++)
            #pragma unroll
            for (int q = 0; q < 4; q++) acc[a][b][q] = 0.f;

    // prologue: stages 0..2
    #pragma unroll
    for (int p = 0; p < 3; p++) {
        const uint32_t st = sb + p * STAGE;
        const size_t go = (size_t)p * 128;   // BK*2 bytes along k
        #pragma unroll
        for (int i = 0; i < 4; i++) {
            CP_ASYNC16(st + OFF_A  + swOff[i], gA  + go + i * RSTRIDE);
            CP_ASYNC16(st + OFF_BH + swOff[i], gBh + go + i * RSTRIDE);
            CP_ASYNC16(st + OFF_BL + swOff[i], gBl + go + i * RSTRIDE);
        }
        CP_COMMIT();
    }

    for (int c = 0; c < NCHUNK; c++) {
        // wait until stage c resident (pending groups: c..min(c+2, NCHUNK-1))
        if (c + 2 < NCHUNK)      CP_WAIT2();
        else if (c + 1 < NCHUNK) CP_WAIT1();
        else                     CP_WAIT0();
        __syncthreads();   // all warps see stage c; all done reading stage (c-1)%4

        if (c + 3 < NCHUNK) {
            const uint32_t st = sb + ((c + 3) % NSTAGE) * STAGE;
            const size_t go = (size_t)(c + 3) * 128;
            #pragma unroll
            for (int i = 0; i < 4; i++) {
                CP_ASYNC16(st + OFF_A  + swOff[i], gA  + go + i * RSTRIDE);
                CP_ASYNC16(st + OFF_BH + swOff[i], gBh + go + i * RSTRIDE);
                CP_ASYNC16(st + OFF_BL + swOff[i], gBl + go + i * RSTRIDE);
            }
            CP_COMMIT();
        }
        const uint32_t st = sb + (c % NSTAGE) * STAGE;
        compute_stage(st + OFF_A, st + OFF_BH, st + OFF_BL,
                      lane, warp_m, warp_n, acc);
    }

    // ---- epilogue: bias + grid activation ----
    const float ls = cbrtf(fabsf(scale_p[0]));
    const int gWarp = ((nBase + warp_n) >> 1);

    #pragma unroll
    for (int mb = 0; mb < 4; mb++) {
        const int rlo = rowBase + warp_m + mb * 16 + (lane >> 2);
        #pragma unroll
        for (int nb = 0; nb < 4; nb++) {
            const int g  = gWarp + nb * 4 + (lane & 3);
            const int c0 = 2 * g;
            const float b0v = bias[c0], b1v = bias[c0 + 1];
            const float* av = act + (size_t)g * 9;
            const float* d = acc[mb][nb];
            const float oLo = act_eval(d[0] + b0v, d[1] + b1v, av);
            const float oHi = act_eval(d[2] + b0v, d[3] + b1v, av);
            if (LAST) {
                const float ob = out_bias[g];
                Yout[(size_t)rlo * NG + g]       = oLo + ob;
                Yout[(size_t)(rlo + 8) * NG + g] = oHi + ob;
            } else {
                Ynext[(size_t)rlo * NG + g]       = __float2half_rn(oLo * ls);
                Ynext[(size_t)(rlo + 8) * NG + g] = __float2half_rn(oHi * ls);
            }
        }
    }
}

extern "C" void kernel_launch(void* const* d_in, const int* in_sizes, int n_in,
                              void* d_out, int out_size)
{
    (void)in_sizes; (void)n_in; (void)out_size;
    const float* X     = (const float*)d_in[0];
    const float* w0    = (const float*)d_in[1];
    const float* b0    = (const float*)d_in[2];
    const float* a0    = (const float*)d_in[3];
    const float* w1    = (const float*)d_in[4];
    const float* b1    = (const float*)d_in[5];
    const float* a1    = (const float*)d_in[6];
    const float* w2    = (const float*)d_in[7];
    const float* b2    = (const float*)d_in[8];
    const float* a2    = (const float*)d_in[9];
    const float* scale = (const float*)d_in[10];
    const float* outb  = (const float*)d_in[11];
    float* out = (float*)d_out;

    __half *A0, *A1, *Bh, *Bl;
    cudaGetSymbolAddress((void**)&A0, g_A0);
    cudaGetSymbolAddress((void**)&A1, g_A1);
    cudaGetSymbolAddress((void**)&Bh, g_Bhi);
    cudaGetSymbolAddress((void**)&Bl, g_Blo);
    const size_t WSTRIDE = (size_t)OUTW * INW;

    cudaFuncSetAttribute(gemm_act<0>, cudaFuncAttributeMaxDynamicSharedMemorySize, SMEM_TOTAL);
    cudaFuncSetAttribute(gemm_act<1>, cudaFuncAttributeMaxDynamicSharedMemorySize, SMEM_TOTAL);

    prep_x<<<(NROWS * INW) / (256 * 4), 256>>>(X, scale, A0);
    dim3 wgrid(INW / 32, OUTW / 32), wblk(32, 8);
    prep_w<<<wgrid, wblk>>>(w0, Bh + 0 * WSTRIDE, Bl + 0 * WSTRIDE);
    prep_w<<<wgrid, wblk>>>(w1, Bh + 1 * WSTRIDE, Bl + 1 * WSTRIDE);
    prep_w<<<wgrid, wblk>>>(w2, Bh + 2 * WSTRIDE, Bl + 2 * WSTRIDE);

    dim3 ggrid(OUTW / BN, NROWS / BM);   // (16, 128)
    gemm_act<0><<<ggrid, 256, SMEM_TOTAL>>>(A0, Bh + 0 * WSTRIDE, Bl + 0 * WSTRIDE,
                                            b0, a0, scale, nullptr, A1, nullptr);
    gemm_act<0><<<ggrid, 256, SMEM_TOTAL>>>(A1, Bh + 1 * WSTRIDE, Bl + 1 * WSTRIDE,
                                            b1, a1, scale, nullptr, A0, nullptr);
    gemm_act<1><<<ggrid, 256, SMEM_TOTAL>>>(A0, Bh + 2 * WSTRIDE, Bl + 2 * WSTRIDE,
                                            b2, a2, scale, outb, nullptr, out);
}

// round 7
// speedup vs baseline: 5.5669x; 1.5987x over previous
#include <cuda_runtime.h>
#include <cuda_fp16.h>
#include <math.h>
#include <stdint.h>

// Problem constants:
//   X: [16384, 1024] fp32; per layer: wpn [2048,2048], b [2048], a [1024,9,1]
//   scale [1], out_bias [1024]; out [16384,1024] fp32
#define NROWS 16384
#define INW   1024
#define OUTW  2048
#define NG    1024

#define BM 128
#define BN 128
#define BK 64
#define NCHUNK (INW / BK)      // 16

// SMEM stage: A (128x64 fp16 = 16KB) + B (16KB)
#define OFF_A  0
#define OFF_B  16384
#define STAGE  32768
#define NSTAGE 4
#define SMEM_TOTAL (NSTAGE * STAGE)   // 131072

// -------- static device buffers (no allocation) --------
__device__ __half g_A0[(size_t)NROWS * INW];
__device__ __half g_A1[(size_t)NROWS * INW];
__device__ __half g_B[3][(size_t)OUTW * INW];

// -------- PTX helpers (legal on compute_100) --------
__device__ __forceinline__ uint32_t smem_u32(const void* p) {
    uint32_t a;
    asm("{ .reg .u64 t; cvta.to.shared.u64 t, %1; cvt.u32.u64 %0, t; }" : "=r"(a) : "l"(p));
    return a;
}
#define CP_ASYNC16(dst, src) \
    asm volatile("cp.async.cg.shared.global [%0], [%1], 16;" :: "r"(dst), "l"(src))
#define CP_COMMIT() asm volatile("cp.async.commit_group;" ::: "memory")
#define CP_WAIT2()  asm volatile("cp.async.wait_group 2;" ::: "memory")
#define CP_WAIT1()  asm volatile("cp.async.wait_group 1;" ::: "memory")
#define CP_WAIT0()  asm volatile("cp.async.wait_group 0;" ::: "memory")

#define LDSM4(r0, r1, r2, r3, addr) \
    asm volatile("ldmatrix.sync.aligned.m8n8.x4.shared.b16 {%0,%1,%2,%3}, [%4];" \
                 : "=r"(r0), "=r"(r1), "=r"(r2), "=r"(r3) : "r"(addr))

#define MMA_F16(d, a, b0, b1) \
    asm volatile("mma.sync.aligned.m16n8k16.row.col.f32.f16.f16.f32 " \
                 "{%0,%1,%2,%3},{%4,%5,%6,%7},{%8,%9},{%0,%1,%2,%3};" \
                 : "+f"((d)[0]), "+f"((d)[1]), "+f"((d)[2]), "+f"((d)[3]) \
                 : "r"((a)[0]), "r"((a)[1]), "r"((a)[2]), "r"((a)[3]), "r"(b0), "r"(b1))

// -------- prep kernels --------
__global__ void prep_x(const float* __restrict__ X, const float* __restrict__ scale_p,
                       __half* __restrict__ A)
{
    const float ls = cbrtf(fabsf(scale_p[0]));
    size_t i = ((size_t)blockIdx.x * 256 + threadIdx.x) * 4;
    float4 v = *(const float4*)(X + i);
    __half2 h01 = __floats2half2_rn(v.x * ls, v.y * ls);
    __half2 h23 = __floats2half2_rn(v.z * ls, v.w * ls);
    *(uint2*)(A + i) = make_uint2(*(uint32_t*)&h01, *(uint32_t*)&h23);
}

// raw_w[k][n] = wpn[k][n] - wpn[k+1024][n]; transposed Bt[n][k] as fp16.
__global__ void prep_w(const float* __restrict__ wpn, __half* __restrict__ B)
{
    __shared__ float t[32][33];
    const int k0 = blockIdx.x * 32, n0 = blockIdx.y * 32;
    const int tx = threadIdx.x, ty = threadIdx.y;   // (32, 8)
    #pragma unroll
    for (int i = 0; i < 32; i += 8) {
        int k = k0 + ty + i, n = n0 + tx;
        t[ty + i][tx] = wpn[(size_t)k * OUTW + n] - wpn[(size_t)(k + INW) * OUTW + n];
    }
    __syncthreads();
    #pragma unroll
    for (int i = 0; i < 32; i += 8) {
        int n = n0 + ty + i, k = k0 + tx;
        B[(size_t)n * INW + k] = __float2half_rn(t[tx][ty + i]);
    }
}

// -------- fused GEMM(fp16, mma.sync) + activation --------
__device__ __forceinline__ void compute_stage(
    uint32_t stA, uint32_t stB,
    int lane, int warp_m, int warp_n, float acc[4][4][4])
{
    const uint32_t swx  = (uint32_t)(lane & 7) * 16;
    const uint32_t rsel = (uint32_t)(lane & 15);
    const uint32_t csel = (uint32_t)(lane >> 4) * 16;
    #pragma unroll
    for (int ks = 0; ks < 4; ks++) {
        const uint32_t col = ((uint32_t)ks * 32 + csel) ^ swx;
        uint32_t ah[4][4], bh[2][4];
        #pragma unroll
        for (int mb = 0; mb < 4; mb++) {
            uint32_t ro = (uint32_t)(warp_m + mb * 16 + rsel) * 128 + col;
            LDSM4(ah[mb][0], ah[mb][1], ah[mb][2], ah[mb][3], stA + ro);
        }
        #pragma unroll
        for (int pb = 0; pb < 2; pb++) {
            uint32_t ro = (uint32_t)(warp_n + pb * 16 + rsel) * 128 + col;
            LDSM4(bh[pb][0], bh[pb][1], bh[pb][2], bh[pb][3], stB + ro);
        }
        #pragma unroll
        for (int mb = 0; mb < 4; mb++)
            #pragma unroll
            for (int nb = 0; nb < 4; nb++) {
                const int pb = nb >> 1, s = nb & 1;
                MMA_F16(acc[mb][nb], ah[mb], bh[pb][s], bh[pb][s + 2]);
            }
    }
}

__device__ __forceinline__ float act_eval(float x0, float x1, const float* __restrict__ av)
{
    x0 = fminf(fmaxf(x0, -1.f), 1.f);
    x1 = fminf(fmaxf(x1, -1.f), 1.f);
    const float lo0 = (x0 < 0.f) ? -1.f : 0.f;
    const float lo1 = (x1 < 0.f) ? -1.f : 0.f;
    const float f0 = x0 - lo0;
    const float f1 = x1 - lo1;
    const int base = ((x0 < 0.f) ? 0 : 1) + 3 * ((x1 < 0.f) ? 0 : 1);
    const float v00 = __ldg(av + base);
    const float v10 = __ldg(av + base + 1);
    const float v01 = __ldg(av + base + 3);
    const float v11 = __ldg(av + base + 4);
    return (1.f - f0) * ((1.f - f1) * v00 + f1 * v01)
         +        f0  * ((1.f - f1) * v10 + f1 * v11);
}

template<int LAST>
__global__ void __launch_bounds__(256, 1)
gemm_act(const __half* __restrict__ A, const __half* __restrict__ B,
         const float* __restrict__ bias, const float* __restrict__ act,
         const float* __restrict__ scale_p, const float* __restrict__ out_bias,
         __half* __restrict__ Ynext, float* __restrict__ Yout)
{
    extern __shared__ __align__(1024) char smem[];
    const uint32_t sb = smem_u32(smem);
    const int tid  = threadIdx.x;
    const int wid  = tid >> 5;
    const int lane = tid & 31;
    const int rowBase = blockIdx.y * BM;
    const int nBase   = blockIdx.x * BN;
    const int warp_m = (wid & 1) * 64;
    const int warp_n = (wid >> 1) * 32;

    // ---- loader mapping: thread -> 4 rows x 1 seg per tile ----
    const int r0   = tid >> 3;            // 0..31
    const int cseg = (tid & 7) * 16;      // byte seg within 128B row
    uint32_t swOff[4];
    #pragma unroll
    for (int i = 0; i < 4; i++)
        swOff[i] = (uint32_t)(r0 + 32 * i) * 128 + ((uint32_t)cseg ^ ((uint32_t)(r0 & 7) * 16));

    const char* gA = (const char*)(A + (size_t)(rowBase + r0) * INW) + cseg;
    const char* gB = (const char*)(B + (size_t)(nBase  + r0) * INW) + cseg;
    const size_t RSTRIDE = (size_t)32 * INW * 2;   // 32 rows

    float acc[4][4][4];
    #pragma unroll
    for (int a = 0; a < 4; a++)
        #pragma unroll
        for (int b = 0; b < 4; b++)
            #pragma unroll
            for (int q = 0; q < 4; q++) acc[a][b][q] = 0.f;

    // prologue: stages 0..2
    #pragma unroll
    for (int p = 0; p < 3; p++) {
        const uint32_t st = sb + p * STAGE;
        const size_t go = (size_t)p * 128;   // BK*2 bytes along k
        #pragma unroll
        for (int i = 0; i < 4; i++) {
            CP_ASYNC16(st + OFF_A + swOff[i], gA + go + i * RSTRIDE);
            CP_ASYNC16(st + OFF_B + swOff[i], gB + go + i * RSTRIDE);
        }
        CP_COMMIT();
    }

    for (int c = 0; c < NCHUNK; c++) {
        if (c + 2 < NCHUNK)      CP_WAIT2();
        else if (c + 1 < NCHUNK) CP_WAIT1();
        else                     CP_WAIT0();
        __syncthreads();   // stage c resident; all warps done reading stage (c-1)%4

        if (c + 3 < NCHUNK) {
            const uint32_t st = sb + ((c + 3) % NSTAGE) * STAGE;
            const size_t go = (size_t)(c + 3) * 128;
            #pragma unroll
            for (int i = 0; i < 4; i++) {
                CP_ASYNC16(st + OFF_A + swOff[i], gA + go + i * RSTRIDE);
                CP_ASYNC16(st + OFF_B + swOff[i], gB + go + i * RSTRIDE);
            }
            CP_COMMIT();
        }
        const uint32_t st = sb + (c % NSTAGE) * STAGE;
        compute_stage(st + OFF_A, st + OFF_B, lane, warp_m, warp_n, acc);
    }

    // ---- epilogue: bias + grid activation ----
    const float ls = cbrtf(fabsf(scale_p[0]));
    const int gWarp = ((nBase + warp_n) >> 1);

    #pragma unroll
    for (int mb = 0; mb < 4; mb++) {
        const int rlo = rowBase + warp_m + mb * 16 + (lane >> 2);
        #pragma unroll
        for (int nb = 0; nb < 4; nb++) {
            const int g  = gWarp + nb * 4 + (lane & 3);
            const int c0 = 2 * g;
            const float b0v = bias[c0], b1v = bias[c0 + 1];
            const float* av = act + (size_t)g * 9;
            const float* d = acc[mb][nb];
            const float oLo = act_eval(d[0] + b0v, d[1] + b1v, av);
            const float oHi = act_eval(d[2] + b0v, d[3] + b1v, av);
            if (LAST) {
                const float ob = out_bias[g];
                Yout[(size_t)rlo * NG + g]       = oLo + ob;
                Yout[(size_t)(rlo + 8) * NG + g] = oHi + ob;
            } else {
                Ynext[(size_t)rlo * NG + g]       = __float2half_rn(oLo * ls);
                Ynext[(size_t)(rlo + 8) * NG + g] = __float2half_rn(oHi * ls);
            }
        }
    }
}

extern "C" void kernel_launch(void* const* d_in, const int* in_sizes, int n_in,
                              void* d_out, int out_size)
{
    (void)in_sizes; (void)n_in; (void)out_size;
    const float* X     = (const float*)d_in[0];
    const float* w0    = (const float*)d_in[1];
    const float* b0    = (const float*)d_in[2];
    const float* a0    = (const float*)d_in[3];
    const float* w1    = (const float*)d_in[4];
    const float* b1    = (const float*)d_in[5];
    const float* a1    = (const float*)d_in[6];
    const float* w2    = (const float*)d_in[7];
    const float* b2    = (const float*)d_in[8];
    const float* a2    = (const float*)d_in[9];
    const float* scale = (const float*)d_in[10];
    const float* outb  = (const float*)d_in[11];
    float* out = (float*)d_out;

    __half *A0, *A1, *B;
    cudaGetSymbolAddress((void**)&A0, g_A0);
    cudaGetSymbolAddress((void**)&A1, g_A1);
    cudaGetSymbolAddress((void**)&B,  g_B);
    const size_t WSTRIDE = (size_t)OUTW * INW;

    cudaFuncSetAttribute(gemm_act<0>, cudaFuncAttributeMaxDynamicSharedMemorySize, SMEM_TOTAL);
    cudaFuncSetAttribute(gemm_act<1>, cudaFuncAttributeMaxDynamicSharedMemorySize, SMEM_TOTAL);

    prep_x<<<(NROWS * INW) / (256 * 4), 256>>>(X, scale, A0);
    dim3 wgrid(INW / 32, OUTW / 32), wblk(32, 8);
    prep_w<<<wgrid, wblk>>>(w0, B + 0 * WSTRIDE);
    prep_w<<<wgrid, wblk>>>(w1, B + 1 * WSTRIDE);
    prep_w<<<wgrid, wblk>>>(w2, B + 2 * WSTRIDE);

    dim3 ggrid(OUTW / BN, NROWS / BM);   // (16, 128)
    gemm_act<0><<<ggrid, 256, SMEM_TOTAL>>>(A0, B + 0 * WSTRIDE,
                                            b0, a0, scale, nullptr, A1, nullptr);
    gemm_act<0><<<ggrid, 256, SMEM_TOTAL>>>(A1, B + 1 * WSTRIDE,
                                            b1, a1, scale, nullptr, A0, nullptr);
    gemm_act<1><<<ggrid, 256, SMEM_TOTAL>>>(A0, B + 2 * WSTRIDE,
                                            b2, a2, scale, outb, nullptr, out);
}

// round 9
// speedup vs baseline: 6.1080x; 1.0972x over previous
#include <cuda_runtime.h>
#include <cuda_fp16.h>
#include <math.h>
#include <stdint.h>

// Problem constants:
//   X: [16384, 1024] fp32; per layer: wpn [2048,2048], b [2048], a [1024,9,1]
//   scale [1], out_bias [1024]; out [16384,1024] fp32
#define NROWS 16384
#define INW   1024
#define OUTW  2048
#define NG    1024

#define BM 128
#define BN 256
#define BK 64
#define NCHUNK (INW / BK)      // 16
#define NTHREADS 512

// SMEM stage: A (128x64 fp16 = 16KB) + B (256x64 fp16 = 32KB)
#define OFF_A  0
#define OFF_B  16384
#define STAGE  49152
#define NSTAGE 4
#define SMEM_TOTAL (NSTAGE * STAGE)   // 196608

// -------- static device buffers (no allocation) --------
__device__ __half g_A0[(size_t)NROWS * INW];
__device__ __half g_A1[(size_t)NROWS * INW];
__device__ __half g_B[3][(size_t)OUTW * INW];

// -------- PTX helpers (legal on compute_100) --------
__device__ __forceinline__ uint32_t smem_u32(const void* p) {
    uint32_t a;
    asm("{ .reg .u64 t; cvta.to.shared.u64 t, %1; cvt.u32.u64 %0, t; }" : "=r"(a) : "l"(p));
    return a;
}
#define CP_ASYNC16(dst, src) \
    asm volatile("cp.async.cg.shared.global [%0], [%1], 16;" :: "r"(dst), "l"(src))
#define CP_COMMIT() asm volatile("cp.async.commit_group;" ::: "memory")
#define CP_WAIT2()  asm volatile("cp.async.wait_group 2;" ::: "memory")
#define CP_WAIT1()  asm volatile("cp.async.wait_group 1;" ::: "memory")
#define CP_WAIT0()  asm volatile("cp.async.wait_group 0;" ::: "memory")

#define LDSM4(r0, r1, r2, r3, addr) \
    asm volatile("ldmatrix.sync.aligned.m8n8.x4.shared.b16 {%0,%1,%2,%3}, [%4];" \
                 : "=r"(r0), "=r"(r1), "=r"(r2), "=r"(r3) : "r"(addr))

#define MMA_F16(d, a, b0, b1) \
    asm volatile("mma.sync.aligned.m16n8k16.row.col.f32.f16.f16.f32 " \
                 "{%0,%1,%2,%3},{%4,%5,%6,%7},{%8,%9},{%0,%1,%2,%3};" \
                 : "+f"((d)[0]), "+f"((d)[1]), "+f"((d)[2]), "+f"((d)[3]) \
                 : "r"((a)[0]), "r"((a)[1]), "r"((a)[2]), "r"((a)[3]), "r"(b0), "r"(b1))

// -------- prep kernels --------
__global__ void prep_x(const float* __restrict__ X, const float* __restrict__ scale_p,
                       __half* __restrict__ A)
{
    const float ls = cbrtf(fabsf(scale_p[0]));
    size_t i = ((size_t)blockIdx.x * 256 + threadIdx.x) * 4;
    float4 v = *(const float4*)(X + i);
    __half2 h01 = __floats2half2_rn(v.x * ls, v.y * ls);
    __half2 h23 = __floats2half2_rn(v.z * ls, v.w * ls);
    *(uint2*)(A + i) = make_uint2(*(uint32_t*)&h01, *(uint32_t*)&h23);
}

// raw_w[k][n] = wpn[k][n] - wpn[k+1024][n]; transposed Bt[n][k] as fp16.
__global__ void prep_w(const float* __restrict__ wpn, __half* __restrict__ B)
{
    __shared__ float t[32][33];
    const int k0 = blockIdx.x * 32, n0 = blockIdx.y * 32;
    const int tx = threadIdx.x, ty = threadIdx.y;   // (32, 8)
    #pragma unroll
    for (int i = 0; i < 32; i += 8) {
        int k = k0 + ty + i, n = n0 + tx;
        t[ty + i][tx] = wpn[(size_t)k * OUTW + n] - wpn[(size_t)(k + INW) * OUTW + n];
    }
    __syncthreads();
    #pragma unroll
    for (int i = 0; i < 32; i += 8) {
        int n = n0 + ty + i, k = k0 + tx;
        B[(size_t)n * INW + k] = __float2half_rn(t[tx][ty + i]);
    }
}

// -------- fused GEMM(fp16, mma.sync) + activation --------
// Low-register-pressure schedule: B frags up-front per ks, A frags
// double-buffered one mb-block ahead of the MMAs consuming them.
__device__ __forceinline__ void compute_stage(
    uint32_t stA, uint32_t stB,
    int lane, int warp_m, int warp_n, float acc[4][4][4])
{
    const uint32_t swx  = (uint32_t)(lane & 7) * 16;
    const uint32_t rsel = (uint32_t)(lane & 15);
    const uint32_t csel = (uint32_t)(lane >> 4) * 16;
    #pragma unroll
    for (int ks = 0; ks < 4; ks++) {
        const uint32_t col = ((uint32_t)ks * 32 + csel) ^ swx;
        uint32_t bh[2][4];
        #pragma unroll
        for (int pb = 0; pb < 2; pb++) {
            uint32_t ro = (uint32_t)(warp_n + pb * 16 + rsel) * 128 + col;
            LDSM4(bh[pb][0], bh[pb][1], bh[pb][2], bh[pb][3], stB + ro);
        }
        uint32_t afr[2][4];
        {
            uint32_t ro = (uint32_t)(warp_m + rsel) * 128 + col;
            LDSM4(afr[0][0], afr[0][1], afr[0][2], afr[0][3], stA + ro);
        }
        #pragma unroll
        for (int mb = 0; mb < 4; mb++) {
            const int cur = mb & 1, nxt = cur ^ 1;
            if (mb < 3) {
                uint32_t ro = (uint32_t)(warp_m + (mb + 1) * 16 + rsel) * 128 + col;
                LDSM4(afr[nxt][0], afr[nxt][1], afr[nxt][2], afr[nxt][3], stA + ro);
            }
            #pragma unroll
            for (int nb = 0; nb < 4; nb++) {
                const int pb = nb >> 1, s = nb & 1;
                MMA_F16(acc[mb][nb], afr[cur], bh[pb][s], bh[pb][s + 2]);
            }
        }
    }
}

__device__ __forceinline__ float act_eval(float x0, float x1, const float* __restrict__ av)
{
    x0 = fminf(fmaxf(x0, -1.f), 1.f);
    x1 = fminf(fmaxf(x1, -1.f), 1.f);
    const float lo0 = (x0 < 0.f) ? -1.f : 0.f;
    const float lo1 = (x1 < 0.f) ? -1.f : 0.f;
    const float f0 = x0 - lo0;
    const float f1 = x1 - lo1;
    const int base = ((x0 < 0.f) ? 0 : 1) + 3 * ((x1 < 0.f) ? 0 : 1);
    const float v00 = __ldg(av + base);
    const float v10 = __ldg(av + base + 1);
    const float v01 = __ldg(av + base + 3);
    const float v11 = __ldg(av + base + 4);
    return (1.f - f0) * ((1.f - f1) * v00 + f1 * v01)
         +        f0  * ((1.f - f1) * v10 + f1 * v11);
}

template<int LAST>
__global__ void __launch_bounds__(NTHREADS, 1)
gemm_act(const __half* __restrict__ A, const __half* __restrict__ B,
         const float* __restrict__ bias, const float* __restrict__ act,
         const float* __restrict__ scale_p, const float* __restrict__ out_bias,
         __half* __restrict__ Ynext, float* __restrict__ Yout)
{
    extern __shared__ __align__(1024) char smem[];
    const uint32_t sb = smem_u32(smem);
    const int tid  = threadIdx.x;
    const int wid  = tid >> 5;
    const int lane = tid & 31;
    const int rowBase = blockIdx.y * BM;
    const int nBase   = blockIdx.x * BN;
    const int warp_m = (wid & 1) * 64;        // {0, 64}
    const int warp_n = (wid >> 1) * 32;       // {0..224}

    // ---- loader mapping: 512 thr; r0 = tid>>3 in 0..63, cseg 16B segment ----
    const int r0   = tid >> 3;
    const int cseg = (tid & 7) * 16;
    const uint32_t swc = (uint32_t)cseg ^ ((uint32_t)(r0 & 7) * 16);
    uint32_t swA[2], swB[4];
    #pragma unroll
    for (int i = 0; i < 2; i++) swA[i] = (uint32_t)(r0 + 64 * i) * 128 + swc;
    #pragma unroll
    for (int i = 0; i < 4; i++) swB[i] = (uint32_t)(r0 + 64 * i) * 128 + swc;

    const char* gA = (const char*)(A + (size_t)(rowBase + r0) * INW) + cseg;
    const char* gB = (const char*)(B + (size_t)(nBase  + r0) * INW) + cseg;
    const size_t RSTRIDE = (size_t)64 * INW * 2;   // 64 rows

    float acc[4][4][4];
    #pragma unroll
    for (int a = 0; a < 4; a++)
        #pragma unroll
        for (int b = 0; b < 4; b++)
            #pragma unroll
            for (int q = 0; q < 4; q++) acc[a][b][q] = 0.f;

    // prologue: stages 0..2
    #pragma unroll
    for (int p = 0; p < 3; p++) {
        const uint32_t st = sb + p * STAGE;
        const size_t go = (size_t)p * 128;   // BK*2 bytes along k
        #pragma unroll
        for (int i = 0; i < 2; i++)
            CP_ASYNC16(st + OFF_A + swA[i], gA + go + i * RSTRIDE);
        #pragma unroll
        for (int i = 0; i < 4; i++)
            CP_ASYNC16(st + OFF_B + swB[i], gB + go + i * RSTRIDE);
        CP_COMMIT();
    }

    for (int c = 0; c < NCHUNK; c++) {
        if (c + 2 < NCHUNK)      CP_WAIT2();
        else if (c + 1 < NCHUNK) CP_WAIT1();
        else                     CP_WAIT0();
        __syncthreads();   // stage c resident; all warps done reading stage (c-1)%4

        if (c + 3 < NCHUNK) {
            const uint32_t st = sb + ((c + 3) % NSTAGE) * STAGE;
            const size_t go = (size_t)(c + 3) * 128;
            #pragma unroll
            for (int i = 0; i < 2; i++)
                CP_ASYNC16(st + OFF_A + swA[i], gA + go + i * RSTRIDE);
            #pragma unroll
            for (int i = 0; i < 4; i++)
                CP_ASYNC16(st + OFF_B + swB[i], gB + go + i * RSTRIDE);
            CP_COMMIT();
        }
        const uint32_t st = sb + (c % NSTAGE) * STAGE;
        compute_stage(st + OFF_A, st + OFF_B, lane, warp_m, warp_n, acc);
    }

    // ---- epilogue: bias + grid activation ----
    const float ls = cbrtf(fabsf(scale_p[0]));
    const int gWarp = ((nBase + warp_n) >> 1);

    #pragma unroll
    for (int mb = 0; mb < 4; mb++) {
        const int rlo = rowBase + warp_m + mb * 16 + (lane >> 2);
        #pragma unroll
        for (int nb = 0; nb < 4; nb++) {
            const int g  = gWarp + nb * 4 + (lane & 3);
            const int c0 = 2 * g;
            const float b0v = bias[c0], b1v = bias[c0 + 1];
            const float* av = act + (size_t)g * 9;
            const float* d = acc[mb][nb];
            const float oLo = act_eval(d[0] + b0v, d[1] + b1v, av);
            const float oHi = act_eval(d[2] + b0v, d[3] + b1v, av);
            if (LAST) {
                const float ob = out_bias[g];
                Yout[(size_t)rlo * NG + g]       = oLo + ob;
                Yout[(size_t)(rlo + 8) * NG + g] = oHi + ob;
            } else {
                Ynext[(size_t)rlo * NG + g]       = __float2half_rn(oLo * ls);
                Ynext[(size_t)(rlo + 8) * NG + g] = __float2half_rn(oHi * ls);
            }
        }
    }
}

extern "C" void kernel_launch(void* const* d_in, const int* in_sizes, int n_in,
                              void* d_out, int out_size)
{
    (void)in_sizes; (void)n_in; (void)out_size;
    const float* X     = (const float*)d_in[0];
    const float* w0    = (const float*)d_in[1];
    const float* b0    = (const float*)d_in[2];
    const float* a0    = (const float*)d_in[3];
    const float* w1    = (const float*)d_in[4];
    const float* b1    = (const float*)d_in[5];
    const float* a1    = (const float*)d_in[6];
    const float* w2    = (const float*)d_in[7];
    const float* b2    = (const float*)d_in[8];
    const float* a2    = (const float*)d_in[9];
    const float* scale = (const float*)d_in[10];
    const float* outb  = (const float*)d_in[11];
    float* out = (float*)d_out;

    __half *A0, *A1, *B;
    cudaGetSymbolAddress((void**)&A0, g_A0);
    cudaGetSymbolAddress((void**)&A1, g_A1);
    cudaGetSymbolAddress((void**)&B,  g_B);
    const size_t WSTRIDE = (size_t)OUTW * INW;

    cudaFuncSetAttribute(gemm_act<0>, cudaFuncAttributeMaxDynamicSharedMemorySize, SMEM_TOTAL);
    cudaFuncSetAttribute(gemm_act<1>, cudaFuncAttributeMaxDynamicSharedMemorySize, SMEM_TOTAL);

    prep_x<<<(NROWS * INW) / (256 * 4), 256>>>(X, scale, A0);
    dim3 wgrid(INW / 32, OUTW / 32), wblk(32, 8);
    prep_w<<<wgrid, wblk>>>(w0, B + 0 * WSTRIDE);
    prep_w<<<wgrid, wblk>>>(w1, B + 1 * WSTRIDE);
    prep_w<<<wgrid, wblk>>>(w2, B + 2 * WSTRIDE);

    dim3 ggrid(OUTW / BN, NROWS / BM);   // (8, 128)
    gemm_act<0><<<ggrid, NTHREADS, SMEM_TOTAL>>>(A0, B + 0 * WSTRIDE,
                                                 b0, a0, scale, nullptr, A1, nullptr);
    gemm_act<0><<<ggrid, NTHREADS, SMEM_TOTAL>>>(A1, B + 1 * WSTRIDE,
                                                 b1, a1, scale, nullptr, A0, nullptr);
    gemm_act<1><<<ggrid, NTHREADS, SMEM_TOTAL>>>(A0, B + 2 * WSTRIDE,
                                                 b2, a2, scale, outb, nullptr, out);
}

// round 11
// speedup vs baseline: 9.2003x; 1.5063x over previous
#include <cuda_runtime.h>
#include <math.h>
#include <stdint.h>

// Problem constants:
//   X: [16384, 1024] fp32; per layer: wpn [2048,2048], b [2048], a [1024,9,1]
//   scale [1], out_bias [1024]; out [16384,1024] fp32
#define NROWS 16384
#define INW   1024
#define OUTW  2048
#define NG    1024

#define BM 128
#define BN 256
#define BK 128                 // int8 elements per chunk (128 bytes/row)
#define NCHUNK (INW / BK)      // 8
#define NTHREADS 512

// SMEM stage: A (128x128 s8 = 16KB) + B (256x128 s8 = 32KB)
#define OFF_A  0
#define OFF_B  16384
#define STAGE  49152
#define NSTAGE 4
#define SMEM_TOTAL (NSTAGE * STAGE)   // 196608

// -------- static device buffers (no allocation) --------
__device__ int8_t g_A0[(size_t)NROWS * INW];
__device__ int8_t g_A1[(size_t)NROWS * INW];
__device__ int8_t g_B[3][(size_t)OUTW * INW];
__device__ unsigned g_umax[4];   // [0..2] = per-layer |raw_w| max bits, [3] = |X| max bits

// -------- PTX helpers (legal on compute_100) --------
__device__ __forceinline__ uint32_t smem_u32(const void* p) {
    uint32_t a;
    asm("{ .reg .u64 t; cvta.to.shared.u64 t, %1; cvt.u32.u64 %0, t; }" : "=r"(a) : "l"(p));
    return a;
}
#define CP_ASYNC16(dst, src) \
    asm volatile("cp.async.cg.shared.global [%0], [%1], 16;" :: "r"(dst), "l"(src))
#define CP_COMMIT() asm volatile("cp.async.commit_group;" ::: "memory")
#define CP_WAIT2()  asm volatile("cp.async.wait_group 2;" ::: "memory")
#define CP_WAIT1()  asm volatile("cp.async.wait_group 1;" ::: "memory")
#define CP_WAIT0()  asm volatile("cp.async.wait_group 0;" ::: "memory")

#define LDSM4(r0, r1, r2, r3, addr) \
    asm volatile("ldmatrix.sync.aligned.m8n8.x4.shared.b16 {%0,%1,%2,%3}, [%4];" \
                 : "=r"(r0), "=r"(r1), "=r"(r2), "=r"(r3) : "r"(addr))

#define MMA_S8(d, a, b0, b1) \
    asm volatile("mma.sync.aligned.m16n8k32.row.col.s32.s8.s8.s32 " \
                 "{%0,%1,%2,%3},{%4,%5,%6,%7},{%8,%9},{%0,%1,%2,%3};" \
                 : "+r"((d)[0]), "+r"((d)[1]), "+r"((d)[2]), "+r"((d)[3]) \
                 : "r"((a)[0]), "r"((a)[1]), "r"((a)[2]), "r"((a)[3]), "r"(b0), "r"(b1))

__device__ __forceinline__ int q8(float v, float qs) {
    int q = __float2int_rn(v * qs);
    return max(-127, min(127, q));
}

// -------- scale reductions --------
__global__ void reset_umax() {
    if (threadIdx.x < 4) g_umax[threadIdx.x] = 0u;
}

__global__ void absmax_x(const float* __restrict__ X) {
    __shared__ float red[32];
    float m = 0.f;
    const size_t stride = (size_t)gridDim.x * blockDim.x * 4;
    for (size_t i = ((size_t)blockIdx.x * blockDim.x + threadIdx.x) * 4;
         i < (size_t)NROWS * INW; i += stride) {
        float4 v = *(const float4*)(X + i);
        m = fmaxf(m, fmaxf(fmaxf(fabsf(v.x), fabsf(v.y)), fmaxf(fabsf(v.z), fabsf(v.w))));
    }
    #pragma unroll
    for (int o = 16; o > 0; o >>= 1) m = fmaxf(m, __shfl_xor_sync(0xFFFFFFFF, m, o));
    if ((threadIdx.x & 31) == 0) red[threadIdx.x >> 5] = m;
    __syncthreads();
    if (threadIdx.x < 32) {
        m = (threadIdx.x < (blockDim.x >> 5)) ? red[threadIdx.x] : 0.f;
        #pragma unroll
        for (int o = 16; o > 0; o >>= 1) m = fmaxf(m, __shfl_xor_sync(0xFFFFFFFF, m, o));
        if (threadIdx.x == 0) atomicMax(&g_umax[3], __float_as_uint(m));
    }
}

__global__ void absmax_w(const float* __restrict__ wpn, int layer) {
    __shared__ float red[32];
    float m = 0.f;
    const size_t total = (size_t)INW * OUTW;
    const size_t stride = (size_t)gridDim.x * blockDim.x;
    for (size_t i = (size_t)blockIdx.x * blockDim.x + threadIdx.x; i < total; i += stride) {
        float w = wpn[i] - wpn[i + total];
        m = fmaxf(m, fabsf(w));
    }
    #pragma unroll
    for (int o = 16; o > 0; o >>= 1) m = fmaxf(m, __shfl_xor_sync(0xFFFFFFFF, m, o));
    if ((threadIdx.x & 31) == 0) red[threadIdx.x >> 5] = m;
    __syncthreads();
    if (threadIdx.x < 32) {
        m = (threadIdx.x < (blockDim.x >> 5)) ? red[threadIdx.x] : 0.f;
        #pragma unroll
        for (int o = 16; o > 0; o >>= 1) m = fmaxf(m, __shfl_xor_sync(0xFFFFFFFF, m, o));
        if (threadIdx.x == 0) atomicMax(&g_umax[layer], __float_as_uint(m));
    }
}

// -------- prep kernels --------
// Layer-0 A: q = round(Xraw / xmax * 127); dequant scale = xmax*ls/127.
__global__ void prep_x(const float* __restrict__ X, int8_t* __restrict__ A)
{
    const float xmax = fmaxf(__uint_as_float(g_umax[3]), 1e-20f);
    const float qs = 127.f / xmax;
    size_t i = ((size_t)blockIdx.x * 256 + threadIdx.x) * 4;
    float4 v = *(const float4*)(X + i);
    uint32_t pk = (uint32_t)(q8(v.x, qs) & 0xFF)
                | ((uint32_t)(q8(v.y, qs) & 0xFF) << 8)
                | ((uint32_t)(q8(v.z, qs) & 0xFF) << 16)
                | ((uint32_t)(q8(v.w, qs) & 0xFF) << 24);
    *(uint32_t*)(A + i) = pk;
}

// raw_w transposed to Bt[n][k], quantized: q = round(w / wmax * 127).
__global__ void prep_w(const float* __restrict__ wpn, int8_t* __restrict__ B, int layer)
{
    __shared__ float t[32][33];
    const float wmax = fmaxf(__uint_as_float(g_umax[layer]), 1e-20f);
    const float qs = 127.f / wmax;
    const int k0 = blockIdx.x * 32, n0 = blockIdx.y * 32;
    const int tid = threadIdx.x;                    // 256
    const int tx = tid & 31, ty = tid >> 5;         // (32, 8)
    #pragma unroll
    for (int i = 0; i < 32; i += 8) {
        int k = k0 + ty + i, n = n0 + tx;
        t[ty + i][tx] = wpn[(size_t)k * OUTW + n] - wpn[(size_t)(k + INW) * OUTW + n];
    }
    __syncthreads();
    const int n = n0 + tx;           // n-local = tx
    const int kg = ty;               // k-group of 4
    uint32_t pk = 0;
    #pragma unroll
    for (int j = 0; j < 4; j++)
        pk |= (uint32_t)(q8(t[kg * 4 + j][tx], qs) & 0xFF) << (8 * j);
    *(uint32_t*)(B + (size_t)n * INW + k0 + kg * 4) = pk;
}

// -------- fused GEMM(int8, mma.sync) + activation --------
// NOTE: with 128-byte rows, the k32-s8 ldmatrix addressing is byte-identical
// to the proven fp16 k16 pattern (4 ks steps of 32 bytes per chunk).
__device__ __forceinline__ void compute_stage(
    uint32_t stA, uint32_t stB,
    int lane, int warp_m, int warp_n, int acc[4][4][4])
{
    const uint32_t swx  = (uint32_t)(lane & 7) * 16;
    const uint32_t rsel = (uint32_t)(lane & 15);
    const uint32_t csel = (uint32_t)(lane >> 4) * 16;
    #pragma unroll
    for (int ks = 0; ks < 4; ks++) {
        const uint32_t col = ((uint32_t)ks * 32 + csel) ^ swx;
        uint32_t bh[2][4];
        #pragma unroll
        for (int pb = 0; pb < 2; pb++) {
            uint32_t ro = (uint32_t)(warp_n + pb * 16 + rsel) * 128 + col;
            LDSM4(bh[pb][0], bh[pb][1], bh[pb][2], bh[pb][3], stB + ro);
        }
        uint32_t afr[2][4];
        {
            uint32_t ro = (uint32_t)(warp_m + rsel) * 128 + col;
            LDSM4(afr[0][0], afr[0][1], afr[0][2], afr[0][3], stA + ro);
        }
        #pragma unroll
        for (int mb = 0; mb < 4; mb++) {
            const int cur = mb & 1, nxt = cur ^ 1;
            if (mb < 3) {
                uint32_t ro = (uint32_t)(warp_m + (mb + 1) * 16 + rsel) * 128 + col;
                LDSM4(afr[nxt][0], afr[nxt][1], afr[nxt][2], afr[nxt][3], stA + ro);
            }
            #pragma unroll
            for (int nb = 0; nb < 4; nb++) {
                const int pb = nb >> 1, s = nb & 1;
                MMA_S8(acc[mb][nb], afr[cur], bh[pb][s], bh[pb][s + 2]);
            }
        }
    }
}

__device__ __forceinline__ float act_eval(float x0, float x1, const float* __restrict__ av)
{
    x0 = fminf(fmaxf(x0, -1.f), 1.f);
    x1 = fminf(fmaxf(x1, -1.f), 1.f);
    const float lo0 = (x0 < 0.f) ? -1.f : 0.f;
    const float lo1 = (x1 < 0.f) ? -1.f : 0.f;
    const float f0 = x0 - lo0;
    const float f1 = x1 - lo1;
    const int base = ((x0 < 0.f) ? 0 : 1) + 3 * ((x1 < 0.f) ? 0 : 1);
    const float v00 = __ldg(av + base);
    const float v10 = __ldg(av + base + 1);
    const float v01 = __ldg(av + base + 3);
    const float v11 = __ldg(av + base + 4);
    return (1.f - f0) * ((1.f - f1) * v00 + f1 * v01)
         +        f0  * ((1.f - f1) * v10 + f1 * v11);
}

template<int LAST, int FIRST>
__global__ void __launch_bounds__(NTHREADS, 1)
gemm_act(const int8_t* __restrict__ A, const int8_t* __restrict__ B, int layer,
         const float* __restrict__ bias, const float* __restrict__ act,
         const float* __restrict__ scale_p, const float* __restrict__ out_bias,
         int8_t* __restrict__ Ynext, float* __restrict__ Yout)
{
    extern __shared__ __align__(1024) char smem[];
    const uint32_t sb = smem_u32(smem);
    const int tid  = threadIdx.x;
    const int wid  = tid >> 5;
    const int lane = tid & 31;
    const int rowBase = blockIdx.y * BM;
    const int nBase   = blockIdx.x * BN;
    const int warp_m = (wid & 1) * 64;        // {0, 64}
    const int warp_n = (wid >> 1) * 32;       // {0..224}

    // ---- loader mapping: 512 thr; r0 = tid>>3 in 0..63, 16B segment ----
    const int r0   = tid >> 3;
    const int cseg = (tid & 7) * 16;
    const uint32_t swc = (uint32_t)cseg ^ ((uint32_t)(r0 & 7) * 16);
    uint32_t swA[2], swB[4];
    #pragma unroll
    for (int i = 0; i < 2; i++) swA[i] = (uint32_t)(r0 + 64 * i) * 128 + swc;
    #pragma unroll
    for (int i = 0; i < 4; i++) swB[i] = (uint32_t)(r0 + 64 * i) * 128 + swc;

    const char* gA = (const char*)(A + (size_t)(rowBase + r0) * INW) + cseg;
    const char* gB = (const char*)(B + (size_t)(nBase  + r0) * INW) + cseg;
    const size_t RSTRIDE = (size_t)64 * INW;   // 64 rows (1 byte/elem)

    int acc[4][4][4];
    #pragma unroll
    for (int a = 0; a < 4; a++)
        #pragma unroll
        for (int b = 0; b < 4; b++)
            #pragma unroll
            for (int q = 0; q < 4; q++) acc[a][b][q] = 0;

    // prologue: stages 0..2
    #pragma unroll
    for (int p = 0; p < 3; p++) {
        const uint32_t st = sb + p * STAGE;
        const size_t go = (size_t)p * 128;   // BK bytes along k
        #pragma unroll
        for (int i = 0; i < 2; i++)
            CP_ASYNC16(st + OFF_A + swA[i], gA + go + i * RSTRIDE);
        #pragma unroll
        for (int i = 0; i < 4; i++)
            CP_ASYNC16(st + OFF_B + swB[i], gB + go + i * RSTRIDE);
        CP_COMMIT();
    }

    for (int c = 0; c < NCHUNK; c++) {
        if (c + 2 < NCHUNK)      CP_WAIT2();
        else if (c + 1 < NCHUNK) CP_WAIT1();
        else                     CP_WAIT0();
        __syncthreads();   // stage c resident; all warps done reading stage (c-1)%4

        if (c + 3 < NCHUNK) {
            const uint32_t st = sb + ((c + 3) % NSTAGE) * STAGE;
            const size_t go = (size_t)(c + 3) * 128;
            #pragma unroll
            for (int i = 0; i < 2; i++)
                CP_ASYNC16(st + OFF_A + swA[i], gA + go + i * RSTRIDE);
            #pragma unroll
            for (int i = 0; i < 4; i++)
                CP_ASYNC16(st + OFF_B + swB[i], gB + go + i * RSTRIDE);
            CP_COMMIT();
        }
        const uint32_t st = sb + (c % NSTAGE) * STAGE;
        compute_stage(st + OFF_A, st + OFF_B, lane, warp_m, warp_n, acc);
    }

    // ---- epilogue: dequant + bias + grid activation ----
    const float ls = cbrtf(fabsf(scale_p[0]));
    const float wmax = fmaxf(__uint_as_float(g_umax[layer]), 1e-20f);
    const float aScale = FIRST ? (fmaxf(__uint_as_float(g_umax[3]), 1e-20f) * ls) : ls;
    const float dq = (aScale / 127.f) * (wmax / 127.f);
    const int gWarp = ((nBase + warp_n) >> 1);

    #pragma unroll
    for (int mb = 0; mb < 4; mb++) {
        const int rlo = rowBase + warp_m + mb * 16 + (lane >> 2);
        #pragma unroll
        for (int nb = 0; nb < 4; nb++) {
            const int g  = gWarp + nb * 4 + (lane & 3);
            const int c0 = 2 * g;
            const float b0v = bias[c0], b1v = bias[c0 + 1];
            const float* av = act + (size_t)g * 9;
            const int* d = acc[mb][nb];
            const float oLo = act_eval((float)d[0] * dq + b0v, (float)d[1] * dq + b1v, av);
            const float oHi = act_eval((float)d[2] * dq + b0v, (float)d[3] * dq + b1v, av);
            if (LAST) {
                const float ob = out_bias[g];
                Yout[(size_t)rlo * NG + g]       = oLo + ob;
                Yout[(size_t)(rlo + 8) * NG + g] = oHi + ob;
            } else {
                // next-layer value = o*ls, scale ls/127 -> q = round(o*127), |o|<=1
                Ynext[(size_t)rlo * NG + g]       = (int8_t)q8(oLo, 127.f);
                Ynext[(size_t)(rlo + 8) * NG + g] = (int8_t)q8(oHi, 127.f);
            }
        }
    }
}

extern "C" void kernel_launch(void* const* d_in, const int* in_sizes, int n_in,
                              void* d_out, int out_size)
{
    (void)in_sizes; (void)n_in; (void)out_size;
    const float* X     = (const float*)d_in[0];
    const float* w0    = (const float*)d_in[1];
    const float* b0    = (const float*)d_in[2];
    const float* a0    = (const float*)d_in[3];
    const float* w1    = (const float*)d_in[4];
    const float* b1    = (const float*)d_in[5];
    const float* a1    = (const float*)d_in[6];
    const float* w2    = (const float*)d_in[7];
    const float* b2    = (const float*)d_in[8];
    const float* a2    = (const float*)d_in[9];
    const float* scale = (const float*)d_in[10];
    const float* outb  = (const float*)d_in[11];
    float* out = (float*)d_out;

    int8_t *A0, *A1, *B;
    cudaGetSymbolAddress((void**)&A0, g_A0);
    cudaGetSymbolAddress((void**)&A1, g_A1);
    cudaGetSymbolAddress((void**)&B,  g_B);
    const size_t WSTRIDE = (size_t)OUTW * INW;

    cudaFuncSetAttribute(gemm_act<0,1>, cudaFuncAttributeMaxDynamicSharedMemorySize, SMEM_TOTAL);
    cudaFuncSetAttribute(gemm_act<0,0>, cudaFuncAttributeMaxDynamicSharedMemorySize, SMEM_TOTAL);
    cudaFuncSetAttribute(gemm_act<1,0>, cudaFuncAttributeMaxDynamicSharedMemorySize, SMEM_TOTAL);

    // scales
    reset_umax<<<1, 32>>>();
    absmax_x<<<1024, 256>>>(X);
    absmax_w<<<1024, 256>>>(w0, 0);
    absmax_w<<<1024, 256>>>(w1, 1);
    absmax_w<<<1024, 256>>>(w2, 2);

    // quantize
    prep_x<<<(NROWS * INW) / (256 * 4), 256>>>(X, A0);
    dim3 wgrid(INW / 32, OUTW / 32);
    prep_w<<<wgrid, 256>>>(w0, B + 0 * WSTRIDE, 0);
    prep_w<<<wgrid, 256>>>(w1, B + 1 * WSTRIDE, 1);
    prep_w<<<wgrid, 256>>>(w2, B + 2 * WSTRIDE, 2);

    dim3 ggrid(OUTW / BN, NROWS / BM);   // (8, 128)
    gemm_act<0,1><<<ggrid, NTHREADS, SMEM_TOTAL>>>(A0, B + 0 * WSTRIDE, 0,
                                                   b0, a0, scale, nullptr, A1, nullptr);
    gemm_act<0,0><<<ggrid, NTHREADS, SMEM_TOTAL>>>(A1, B + 1 * WSTRIDE, 1,
                                                   b1, a1, scale, nullptr, A0, nullptr);
    gemm_act<1,0><<<ggrid, NTHREADS, SMEM_TOTAL>>>(A0, B + 2 * WSTRIDE, 2,
                                                   b2, a2, scale, outb, nullptr, out);
}

// round 12
// speedup vs baseline: 10.3020x; 1.1197x over previous
#include <cuda_runtime.h>
#include <math.h>
#include <stdint.h>

// Problem constants:
//   X: [16384, 1024] fp32; per layer: wpn [2048,2048], b [2048], a [1024,9,1]
//   scale [1], out_bias [1024]; out [16384,1024] fp32
#define NROWS 16384
#define INW   1024
#define OUTW  2048
#define NG    1024

#define BM 128
#define BN 128
#define BK 128                 // int8 elements per chunk (128 bytes/row)
#define NCHUNK (INW / BK)      // 8
#define NTHREADS 256

// SMEM stage: A (128x128 s8 = 16KB) + B (128x128 s8 = 16KB)
#define OFF_A  0
#define OFF_B  16384
#define STAGE  32768
#define NSTAGE 3
#define SMEM_TOTAL (NSTAGE * STAGE)   // 98304 -> 2 CTAs/SM

// -------- static device buffers (no allocation) --------
__device__ int8_t g_A0[(size_t)NROWS * INW];
__device__ int8_t g_A1[(size_t)NROWS * INW];
__device__ int8_t g_B[3][(size_t)OUTW * INW];
__device__ unsigned g_umax[4];   // [0..2] = per-layer |raw_w| max bits, [3] = |X| max bits

// -------- PTX helpers (legal on compute_100) --------
__device__ __forceinline__ uint32_t smem_u32(const void* p) {
    uint32_t a;
    asm("{ .reg .u64 t; cvta.to.shared.u64 t, %1; cvt.u32.u64 %0, t; }" : "=r"(a) : "l"(p));
    return a;
}
#define CP_ASYNC16(dst, src) \
    asm volatile("cp.async.cg.shared.global [%0], [%1], 16;" :: "r"(dst), "l"(src))
#define CP_COMMIT() asm volatile("cp.async.commit_group;" ::: "memory")
#define CP_WAIT1()  asm volatile("cp.async.wait_group 1;" ::: "memory")
#define CP_WAIT0()  asm volatile("cp.async.wait_group 0;" ::: "memory")

#define LDSM4(r0, r1, r2, r3, addr) \
    asm volatile("ldmatrix.sync.aligned.m8n8.x4.shared.b16 {%0,%1,%2,%3}, [%4];" \
                 : "=r"(r0), "=r"(r1), "=r"(r2), "=r"(r3) : "r"(addr))

#define MMA_S8(d, a, b0, b1) \
    asm volatile("mma.sync.aligned.m16n8k32.row.col.s32.s8.s8.s32 " \
                 "{%0,%1,%2,%3},{%4,%5,%6,%7},{%8,%9},{%0,%1,%2,%3};" \
                 : "+r"((d)[0]), "+r"((d)[1]), "+r"((d)[2]), "+r"((d)[3]) \
                 : "r"((a)[0]), "r"((a)[1]), "r"((a)[2]), "r"((a)[3]), "r"(b0), "r"(b1))

__device__ __forceinline__ int q8(float v, float qs) {
    int q = __float2int_rn(v * qs);
    return max(-127, min(127, q));
}

// -------- scale reductions --------
__global__ void reset_umax() {
    if (threadIdx.x < 4) g_umax[threadIdx.x] = 0u;
}

__global__ void absmax_x(const float* __restrict__ X) {
    __shared__ float red[32];
    float m = 0.f;
    const size_t stride = (size_t)gridDim.x * blockDim.x * 4;
    for (size_t i = ((size_t)blockIdx.x * blockDim.x + threadIdx.x) * 4;
         i < (size_t)NROWS * INW; i += stride) {
        float4 v = *(const float4*)(X + i);
        m = fmaxf(m, fmaxf(fmaxf(fabsf(v.x), fabsf(v.y)), fmaxf(fabsf(v.z), fabsf(v.w))));
    }
    #pragma unroll
    for (int o = 16; o > 0; o >>= 1) m = fmaxf(m, __shfl_xor_sync(0xFFFFFFFF, m, o));
    if ((threadIdx.x & 31) == 0) red[threadIdx.x >> 5] = m;
    __syncthreads();
    if (threadIdx.x < 32) {
        m = (threadIdx.x < (blockDim.x >> 5)) ? red[threadIdx.x] : 0.f;
        #pragma unroll
        for (int o = 16; o > 0; o >>= 1) m = fmaxf(m, __shfl_xor_sync(0xFFFFFFFF, m, o));
        if (threadIdx.x == 0) atomicMax(&g_umax[3], __float_as_uint(m));
    }
}

// all 3 layers in one launch; vectorized float4 loads
__global__ void absmax_w3(const float* __restrict__ w0p, const float* __restrict__ w1p,
                          const float* __restrict__ w2p) {
    __shared__ float red[32];
    const int layer = blockIdx.y;
    const float* wpn = (layer == 0) ? w0p : (layer == 1) ? w1p : w2p;
    const size_t total = (size_t)INW * OUTW;
    float m = 0.f;
    const size_t stride = (size_t)gridDim.x * blockDim.x * 4;
    for (size_t i = ((size_t)blockIdx.x * blockDim.x + threadIdx.x) * 4; i < total; i += stride) {
        float4 h = *(const float4*)(wpn + i);
        float4 l = *(const float4*)(wpn + i + total);
        m = fmaxf(m, fmaxf(fmaxf(fabsf(h.x - l.x), fabsf(h.y - l.y)),
                           fmaxf(fabsf(h.z - l.z), fabsf(h.w - l.w))));
    }
    #pragma unroll
    for (int o = 16; o > 0; o >>= 1) m = fmaxf(m, __shfl_xor_sync(0xFFFFFFFF, m, o));
    if ((threadIdx.x & 31) == 0) red[threadIdx.x >> 5] = m;
    __syncthreads();
    if (threadIdx.x < 32) {
        m = (threadIdx.x < (blockDim.x >> 5)) ? red[threadIdx.x] : 0.f;
        #pragma unroll
        for (int o = 16; o > 0; o >>= 1) m = fmaxf(m, __shfl_xor_sync(0xFFFFFFFF, m, o));
        if (threadIdx.x == 0) atomicMax(&g_umax[layer], __float_as_uint(m));
    }
}

// -------- prep kernels --------
__global__ void prep_x(const float* __restrict__ X, int8_t* __restrict__ A)
{
    const float xmax = fmaxf(__uint_as_float(g_umax[3]), 1e-20f);
    const float qs = 127.f / xmax;
    size_t i = ((size_t)blockIdx.x * 256 + threadIdx.x) * 4;
    float4 v = *(const float4*)(X + i);
    uint32_t pk = (uint32_t)(q8(v.x, qs) & 0xFF)
                | ((uint32_t)(q8(v.y, qs) & 0xFF) << 8)
                | ((uint32_t)(q8(v.z, qs) & 0xFF) << 16)
                | ((uint32_t)(q8(v.w, qs) & 0xFF) << 24);
    *(uint32_t*)(A + i) = pk;
}

// raw_w transposed to Bt[n][k] quantized; all 3 layers in one launch (blockIdx.z).
__global__ void prep_w3(const float* __restrict__ w0p, const float* __restrict__ w1p,
                        const float* __restrict__ w2p, int8_t* __restrict__ Bbase)
{
    __shared__ float t[32][33];
    const int layer = blockIdx.z;
    const float* wpn = (layer == 0) ? w0p : (layer == 1) ? w1p : w2p;
    int8_t* B = Bbase + (size_t)layer * OUTW * INW;
    const float wmax = fmaxf(__uint_as_float(g_umax[layer]), 1e-20f);
    const float qs = 127.f / wmax;
    const int k0 = blockIdx.x * 32, n0 = blockIdx.y * 32;
    const int tid = threadIdx.x;                    // 256
    const int tx = tid & 31, ty = tid >> 5;         // (32, 8)
    #pragma unroll
    for (int i = 0; i < 32; i += 8) {
        int k = k0 + ty + i, n = n0 + tx;
        t[ty + i][tx] = wpn[(size_t)k * OUTW + n] - wpn[(size_t)(k + INW) * OUTW + n];
    }
    __syncthreads();
    const int n = n0 + tx;
    const int kg = ty;               // k-group of 4
    uint32_t pk = 0;
    #pragma unroll
    for (int j = 0; j < 4; j++)
        pk |= (uint32_t)(q8(t[kg * 4 + j][tx], qs) & 0xFF) << (8 * j);
    *(uint32_t*)(B + (size_t)n * INW + k0 + kg * 4) = pk;
}

// -------- fused GEMM(int8, mma.sync) + activation --------
__device__ __forceinline__ void compute_stage(
    uint32_t stA, uint32_t stB,
    int lane, int warp_m, int warp_n, int acc[4][4][4])
{
    const uint32_t swx  = (uint32_t)(lane & 7) * 16;
    const uint32_t rsel = (uint32_t)(lane & 15);
    const uint32_t csel = (uint32_t)(lane >> 4) * 16;
    #pragma unroll
    for (int ks = 0; ks < 4; ks++) {
        const uint32_t col = ((uint32_t)ks * 32 + csel) ^ swx;
        uint32_t bh[2][4];
        #pragma unroll
        for (int pb = 0; pb < 2; pb++) {
            uint32_t ro = (uint32_t)(warp_n + pb * 16 + rsel) * 128 + col;
            LDSM4(bh[pb][0], bh[pb][1], bh[pb][2], bh[pb][3], stB + ro);
        }
        uint32_t afr[2][4];
        {
            uint32_t ro = (uint32_t)(warp_m + rsel) * 128 + col;
            LDSM4(afr[0][0], afr[0][1], afr[0][2], afr[0][3], stA + ro);
        }
        #pragma unroll
        for (int mb = 0; mb < 4; mb++) {
            const int cur = mb & 1, nxt = cur ^ 1;
            if (mb < 3) {
                uint32_t ro = (uint32_t)(warp_m + (mb + 1) * 16 + rsel) * 128 + col;
                LDSM4(afr[nxt][0], afr[nxt][1], afr[nxt][2], afr[nxt][3], stA + ro);
            }
            #pragma unroll
            for (int nb = 0; nb < 4; nb++) {
                const int pb = nb >> 1, s = nb & 1;
                MMA_S8(acc[mb][nb], afr[cur], bh[pb][s], bh[pb][s + 2]);
            }
        }
    }
}

__device__ __forceinline__ float act_eval(float x0, float x1, const float* __restrict__ av)
{
    x0 = fminf(fmaxf(x0, -1.f), 1.f);
    x1 = fminf(fmaxf(x1, -1.f), 1.f);
    const float lo0 = (x0 < 0.f) ? -1.f : 0.f;
    const float lo1 = (x1 < 0.f) ? -1.f : 0.f;
    const float f0 = x0 - lo0;
    const float f1 = x1 - lo1;
    const int base = ((x0 < 0.f) ? 0 : 1) + 3 * ((x1 < 0.f) ? 0 : 1);
    const float v00 = __ldg(av + base);
    const float v10 = __ldg(av + base + 1);
    const float v01 = __ldg(av + base + 3);
    const float v11 = __ldg(av + base + 4);
    return (1.f - f0) * ((1.f - f1) * v00 + f1 * v01)
         +        f0  * ((1.f - f1) * v10 + f1 * v11);
}

template<int LAST, int FIRST>
__global__ void __launch_bounds__(NTHREADS, 2)
gemm_act(const int8_t* __restrict__ A, const int8_t* __restrict__ B, int layer,
         const float* __restrict__ bias, const float* __restrict__ act,
         const float* __restrict__ scale_p, const float* __restrict__ out_bias,
         int8_t* __restrict__ Ynext, float* __restrict__ Yout)
{
    extern __shared__ __align__(1024) char smem[];
    const uint32_t sb = smem_u32(smem);
    const int tid  = threadIdx.x;
    const int wid  = tid >> 5;
    const int lane = tid & 31;
    const int rowBase = blockIdx.y * BM;
    const int nBase   = blockIdx.x * BN;
    const int warp_m = (wid & 1) * 64;        // {0, 64}
    const int warp_n = (wid >> 1) * 32;       // {0, 32, 64, 96}

    // ---- loader mapping: 256 thr; r0 = tid>>3 in 0..31, 16B segment ----
    const int r0   = tid >> 3;
    const int cseg = (tid & 7) * 16;
    const uint32_t swc = (uint32_t)cseg ^ ((uint32_t)(r0 & 7) * 16);
    uint32_t swOff[4];
    #pragma unroll
    for (int i = 0; i < 4; i++)
        swOff[i] = (uint32_t)(r0 + 32 * i) * 128 + swc;

    const char* gA = (const char*)(A + (size_t)(rowBase + r0) * INW) + cseg;
    const char* gB = (const char*)(B + (size_t)(nBase  + r0) * INW) + cseg;
    const size_t RSTRIDE = (size_t)32 * INW;   // 32 rows (1 byte/elem)

    int acc[4][4][4];
    #pragma unroll
    for (int a = 0; a < 4; a++)
        #pragma unroll
        for (int b = 0; b < 4; b++)
            #pragma unroll
            for (int q = 0; q < 4; q++) acc[a][b][q] = 0;

    // prologue: stages 0..1
    #pragma unroll
    for (int p = 0; p < 2; p++) {
        const uint32_t st = sb + p * STAGE;
        const size_t go = (size_t)p * 128;   // BK bytes along k
        #pragma unroll
        for (int i = 0; i < 4; i++) {
            CP_ASYNC16(st + OFF_A + swOff[i], gA + go + i * RSTRIDE);
            CP_ASYNC16(st + OFF_B + swOff[i], gB + go + i * RSTRIDE);
        }
        CP_COMMIT();
    }

    for (int c = 0; c < NCHUNK; c++) {
        if (c + 1 < NCHUNK) CP_WAIT1();
        else                CP_WAIT0();
        __syncthreads();   // stage c resident; all warps done reading stage (c-1)%3

        if (c + 2 < NCHUNK) {
            const uint32_t st = sb + ((c + 2) % NSTAGE) * STAGE;
            const size_t go = (size_t)(c + 2) * 128;
            #pragma unroll
            for (int i = 0; i < 4; i++) {
                CP_ASYNC16(st + OFF_A + swOff[i], gA + go + i * RSTRIDE);
                CP_ASYNC16(st + OFF_B + swOff[i], gB + go + i * RSTRIDE);
            }
            CP_COMMIT();
        }
        const uint32_t st = sb + (c % NSTAGE) * STAGE;
        compute_stage(st + OFF_A, st + OFF_B, lane, warp_m, warp_n, acc);
    }

    // ---- epilogue: dequant + bias + grid activation ----
    const float ls = cbrtf(fabsf(scale_p[0]));
    const float wmax = fmaxf(__uint_as_float(g_umax[layer]), 1e-20f);
    const float aScale = FIRST ? (fmaxf(__uint_as_float(g_umax[3]), 1e-20f) * ls) : ls;
    const float dq = (aScale / 127.f) * (wmax / 127.f);
    const int gWarp = ((nBase + warp_n) >> 1);

    #pragma unroll
    for (int mb = 0; mb < 4; mb++) {
        const int rlo = rowBase + warp_m + mb * 16 + (lane >> 2);
        #pragma unroll
        for (int nb = 0; nb < 4; nb++) {
            const int g  = gWarp + nb * 4 + (lane & 3);
            const int c0 = 2 * g;
            const float b0v = bias[c0], b1v = bias[c0 + 1];
            const float* av = act + (size_t)g * 9;
            const int* d = acc[mb][nb];
            const float oLo = act_eval((float)d[0] * dq + b0v, (float)d[1] * dq + b1v, av);
            const float oHi = act_eval((float)d[2] * dq + b0v, (float)d[3] * dq + b1v, av);
            if (LAST) {
                const float ob = out_bias[g];
                Yout[(size_t)rlo * NG + g]       = oLo + ob;
                Yout[(size_t)(rlo + 8) * NG + g] = oHi + ob;
            } else {
                Ynext[(size_t)rlo * NG + g]       = (int8_t)q8(oLo, 127.f);
                Ynext[(size_t)(rlo + 8) * NG + g] = (int8_t)q8(oHi, 127.f);
            }
        }
    }
}

extern "C" void kernel_launch(void* const* d_in, const int* in_sizes, int n_in,
                              void* d_out, int out_size)
{
    (void)in_sizes; (void)n_in; (void)out_size;
    const float* X     = (const float*)d_in[0];
    const float* w0    = (const float*)d_in[1];
    const float* b0    = (const float*)d_in[2];
    const float* a0    = (const float*)d_in[3];
    const float* w1    = (const float*)d_in[4];
    const float* b1    = (const float*)d_in[5];
    const float* a1    = (const float*)d_in[6];
    const float* w2    = (const float*)d_in[7];
    const float* b2    = (const float*)d_in[8];
    const float* a2    = (const float*)d_in[9];
    const float* scale = (const float*)d_in[10];
    const float* outb  = (const float*)d_in[11];
    float* out = (float*)d_out;

    int8_t *A0, *A1, *B;
    cudaGetSymbolAddress((void**)&A0, g_A0);
    cudaGetSymbolAddress((void**)&A1, g_A1);
    cudaGetSymbolAddress((void**)&B,  g_B);
    const size_t WSTRIDE = (size_t)OUTW * INW;

    cudaFuncSetAttribute(gemm_act<0,1>, cudaFuncAttributeMaxDynamicSharedMemorySize, SMEM_TOTAL);
    cudaFuncSetAttribute(gemm_act<0,0>, cudaFuncAttributeMaxDynamicSharedMemorySize, SMEM_TOTAL);
    cudaFuncSetAttribute(gemm_act<1,0>, cudaFuncAttributeMaxDynamicSharedMemorySize, SMEM_TOTAL);

    // scales
    reset_umax<<<1, 32>>>();
    absmax_x<<<1024, 256>>>(X);
    absmax_w3<<<dim3(256, 3), 256>>>(w0, w1, w2);

    // quantize
    prep_x<<<(NROWS * INW) / (256 * 4), 256>>>(X, A0);
    prep_w3<<<dim3(INW / 32, OUTW / 32, 3), 256>>>(w0, w1, w2, B);

    dim3 ggrid(OUTW / BN, NROWS / BM);   // (16, 128)
    gemm_act<0,1><<<ggrid, NTHREADS, SMEM_TOTAL>>>(A0, B + 0 * WSTRIDE, 0,
                                                   b0, a0, scale, nullptr, A1, nullptr);
    gemm_act<0,0><<<ggrid, NTHREADS, SMEM_TOTAL>>>(A1, B + 1 * WSTRIDE, 1,
                                                   b1, a1, scale, nullptr, A0, nullptr);
    gemm_act<1,0><<<ggrid, NTHREADS, SMEM_TOTAL>>>(A0, B + 2 * WSTRIDE, 2,
                                                   b2, a2, scale, outb, nullptr, out);
}

// round 13
// speedup vs baseline: 10.9192x; 1.0599x over previous
#include <cuda_runtime.h>
#include <math.h>
#include <stdint.h>

// Problem constants:
//   X: [16384, 1024] fp32; per layer: wpn [2048,2048], b [2048], a [1024,9,1]
//   scale [1], out_bias [1024]; out [16384,1024] fp32
#define NROWS 16384
#define INW   1024
#define OUTW  2048
#define NG    1024

#define BM 128
#define BN 128
#define BK 128                 // int8 elements per chunk (128 bytes/row)
#define NCHUNK (INW / BK)      // 8
#define NTHREADS 256

// SMEM stage: A (128x128 s8 = 16KB) + B (128x128 s8 = 16KB)
#define OFF_A  0
#define OFF_B  16384
#define STAGE  32768
#define NSTAGE 3
#define SMEM_TOTAL (NSTAGE * STAGE)   // 98304 -> 2 CTAs/SM

// epilogue staging: [128 rows][64 cols] int8, stride 80 (16B-aligned, conflict-free)
#define STG_STRIDE 80

// -------- static device buffers (no allocation) --------
__device__ int8_t g_A0[(size_t)NROWS * INW];
__device__ int8_t g_A1[(size_t)NROWS * INW];
__device__ int8_t g_B[3][(size_t)OUTW * INW];
__device__ unsigned g_umax[4];   // [0..2] = per-layer |raw_w| max bits, [3] = |X| max bits

// -------- PTX helpers (legal on compute_100) --------
__device__ __forceinline__ uint32_t smem_u32(const void* p) {
    uint32_t a;
    asm("{ .reg .u64 t; cvta.to.shared.u64 t, %1; cvt.u32.u64 %0, t; }" : "=r"(a) : "l"(p));
    return a;
}
#define CP_ASYNC16(dst, src) \
    asm volatile("cp.async.cg.shared.global [%0], [%1], 16;" :: "r"(dst), "l"(src))
#define CP_COMMIT() asm volatile("cp.async.commit_group;" ::: "memory")
#define CP_WAIT1()  asm volatile("cp.async.wait_group 1;" ::: "memory")
#define CP_WAIT0()  asm volatile("cp.async.wait_group 0;" ::: "memory")

#define LDSM4(r0, r1, r2, r3, addr) \
    asm volatile("ldmatrix.sync.aligned.m8n8.x4.shared.b16 {%0,%1,%2,%3}, [%4];" \
                 : "=r"(r0), "=r"(r1), "=r"(r2), "=r"(r3) : "r"(addr))

#define MMA_S8(d, a, b0, b1) \
    asm volatile("mma.sync.aligned.m16n8k32.row.col.s32.s8.s8.s32 " \
                 "{%0,%1,%2,%3},{%4,%5,%6,%7},{%8,%9},{%0,%1,%2,%3};" \
                 : "+r"((d)[0]), "+r"((d)[1]), "+r"((d)[2]), "+r"((d)[3]) \
                 : "r"((a)[0]), "r"((a)[1]), "r"((a)[2]), "r"((a)[3]), "r"(b0), "r"(b1))

__device__ __forceinline__ int q8(float v, float qs) {
    int q = __float2int_rn(v * qs);
    return max(-127, min(127, q));
}

// -------- scale reductions --------
__global__ void reset_umax() {
    if (threadIdx.x < 4) g_umax[threadIdx.x] = 0u;
}

__global__ void absmax_x(const float* __restrict__ X) {
    __shared__ float red[32];
    float m = 0.f;
    const size_t stride = (size_t)gridDim.x * blockDim.x * 4;
    for (size_t i = ((size_t)blockIdx.x * blockDim.x + threadIdx.x) * 4;
         i < (size_t)NROWS * INW; i += stride) {
        float4 v = *(const float4*)(X + i);
        m = fmaxf(m, fmaxf(fmaxf(fabsf(v.x), fabsf(v.y)), fmaxf(fabsf(v.z), fabsf(v.w))));
    }
    #pragma unroll
    for (int o = 16; o > 0; o >>= 1) m = fmaxf(m, __shfl_xor_sync(0xFFFFFFFF, m, o));
    if ((threadIdx.x & 31) == 0) red[threadIdx.x >> 5] = m;
    __syncthreads();
    if (threadIdx.x < 32) {
        m = (threadIdx.x < (blockDim.x >> 5)) ? red[threadIdx.x] : 0.f;
        #pragma unroll
        for (int o = 16; o > 0; o >>= 1) m = fmaxf(m, __shfl_xor_sync(0xFFFFFFFF, m, o));
        if (threadIdx.x == 0) atomicMax(&g_umax[3], __float_as_uint(m));
    }
}

// all 3 layers in one launch; vectorized float4 loads
__global__ void absmax_w3(const float* __restrict__ w0p, const float* __restrict__ w1p,
                          const float* __restrict__ w2p) {
    __shared__ float red[32];
    const int layer = blockIdx.y;
    const float* wpn = (layer == 0) ? w0p : (layer == 1) ? w1p : w2p;
    const size_t total = (size_t)INW * OUTW;
    float m = 0.f;
    const size_t stride = (size_t)gridDim.x * blockDim.x * 4;
    for (size_t i = ((size_t)blockIdx.x * blockDim.x + threadIdx.x) * 4; i < total; i += stride) {
        float4 h = *(const float4*)(wpn + i);
        float4 l = *(const float4*)(wpn + i + total);
        m = fmaxf(m, fmaxf(fmaxf(fabsf(h.x - l.x), fabsf(h.y - l.y)),
                           fmaxf(fabsf(h.z - l.z), fabsf(h.w - l.w))));
    }
    #pragma unroll
    for (int o = 16; o > 0; o >>= 1) m = fmaxf(m, __shfl_xor_sync(0xFFFFFFFF, m, o));
    if ((threadIdx.x & 31) == 0) red[threadIdx.x >> 5] = m;
    __syncthreads();
    if (threadIdx.x < 32) {
        m = (threadIdx.x < (blockDim.x >> 5)) ? red[threadIdx.x] : 0.f;
        #pragma unroll
        for (int o = 16; o > 0; o >>= 1) m = fmaxf(m, __shfl_xor_sync(0xFFFFFFFF, m, o));
        if (threadIdx.x == 0) atomicMax(&g_umax[layer], __float_as_uint(m));
    }
}

// -------- prep kernels --------
// 16 floats in -> 16 bytes out per thread (uint4 store)
__global__ void prep_x(const float* __restrict__ X, int8_t* __restrict__ A)
{
    const float xmax = fmaxf(__uint_as_float(g_umax[3]), 1e-20f);
    const float qs = 127.f / xmax;
    size_t i = ((size_t)blockIdx.x * 256 + threadIdx.x) * 16;
    uint32_t pk[4];
    #pragma unroll
    for (int q = 0; q < 4; q++) {
        float4 v = *(const float4*)(X + i + q * 4);
        pk[q] = (uint32_t)(q8(v.x, qs) & 0xFF)
              | ((uint32_t)(q8(v.y, qs) & 0xFF) << 8)
              | ((uint32_t)(q8(v.z, qs) & 0xFF) << 16)
              | ((uint32_t)(q8(v.w, qs) & 0xFF) << 24);
    }
    *(uint4*)(A + i) = make_uint4(pk[0], pk[1], pk[2], pk[3]);
}

// raw_w transposed to Bt[n][k] quantized; tile 32k x 128n, float4 loads, uint4 stores.
__global__ void prep_w3(const float* __restrict__ w0p, const float* __restrict__ w1p,
                        const float* __restrict__ w2p, int8_t* __restrict__ Bbase)
{
    __shared__ float t[32][129];
    const int layer = blockIdx.z;
    const float* wpn = (layer == 0) ? w0p : (layer == 1) ? w1p : w2p;
    int8_t* B = Bbase + (size_t)layer * OUTW * INW;
    const float wmax = fmaxf(__uint_as_float(g_umax[layer]), 1e-20f);
    const float qs = 127.f / wmax;
    const int k0 = blockIdx.x * 32, n0 = blockIdx.y * 128;
    const int tid = threadIdx.x;                    // 256
    const size_t total = (size_t)INW * OUTW;

    // load: 32 rows x 128 floats; thread: row = tid>>3, col4 = (tid&7) + 8*it
    const int lrow = tid >> 3, lc = tid & 7;
    #pragma unroll
    for (int it = 0; it < 4; it++) {
        const int c4 = (lc + 8 * it) * 4;
        const float* p = wpn + (size_t)(k0 + lrow) * OUTW + n0 + c4;
        float4 h = *(const float4*)p;
        float4 l = *(const float4*)(p + total);
        t[lrow][c4 + 0] = h.x - l.x;
        t[lrow][c4 + 1] = h.y - l.y;
        t[lrow][c4 + 2] = h.z - l.z;
        t[lrow][c4 + 3] = h.w - l.w;
    }
    __syncthreads();
    // store: n = tid>>1 (0..127), kh = tid&1 (16 k each) -> uint4
    const int n = tid >> 1, kh = tid & 1;
    uint32_t pk[4];
    #pragma unroll
    for (int q = 0; q < 4; q++) {
        uint32_t v = 0;
        #pragma unroll
        for (int j = 0; j < 4; j++)
            v |= (uint32_t)(q8(t[kh * 16 + q * 4 + j][n], qs) & 0xFF) << (8 * j);
        pk[q] = v;
    }
    *(uint4*)(B + (size_t)(n0 + n) * INW + k0 + kh * 16) = make_uint4(pk[0], pk[1], pk[2], pk[3]);
}

// -------- fused GEMM(int8, mma.sync) + activation --------
__device__ __forceinline__ void compute_stage(
    uint32_t stA, uint32_t stB,
    int lane, int warp_m, int warp_n, int acc[4][4][4])
{
    const uint32_t swx  = (uint32_t)(lane & 7) * 16;
    const uint32_t rsel = (uint32_t)(lane & 15);
    const uint32_t csel = (uint32_t)(lane >> 4) * 16;
    #pragma unroll
    for (int ks = 0; ks < 4; ks++) {
        const uint32_t col = ((uint32_t)ks * 32 + csel) ^ swx;
        uint32_t bh[2][4];
        #pragma unroll
        for (int pb = 0; pb < 2; pb++) {
            uint32_t ro = (uint32_t)(warp_n + pb * 16 + rsel) * 128 + col;
            LDSM4(bh[pb][0], bh[pb][1], bh[pb][2], bh[pb][3], stB + ro);
        }
        uint32_t afr[2][4];
        {
            uint32_t ro = (uint32_t)(warp_m + rsel) * 128 + col;
            LDSM4(afr[0][0], afr[0][1], afr[0][2], afr[0][3], stA + ro);
        }
        #pragma unroll
        for (int mb = 0; mb < 4; mb++) {
            const int cur = mb & 1, nxt = cur ^ 1;
            if (mb < 3) {
                uint32_t ro = (uint32_t)(warp_m + (mb + 1) * 16 + rsel) * 128 + col;
                LDSM4(afr[nxt][0], afr[nxt][1], afr[nxt][2], afr[nxt][3], stA + ro);
            }
            #pragma unroll
            for (int nb = 0; nb < 4; nb++) {
                const int pb = nb >> 1, s = nb & 1;
                MMA_S8(acc[mb][nb], afr[cur], bh[pb][s], bh[pb][s + 2]);
            }
        }
    }
}

__device__ __forceinline__ float act_eval(float x0, float x1, const float* __restrict__ av)
{
    x0 = fminf(fmaxf(x0, -1.f), 1.f);
    x1 = fminf(fmaxf(x1, -1.f), 1.f);
    const float lo0 = (x0 < 0.f) ? -1.f : 0.f;
    const float lo1 = (x1 < 0.f) ? -1.f : 0.f;
    const float f0 = x0 - lo0;
    const float f1 = x1 - lo1;
    const int base = ((x0 < 0.f) ? 0 : 1) + 3 * ((x1 < 0.f) ? 0 : 1);
    const float v00 = __ldg(av + base);
    const float v10 = __ldg(av + base + 1);
    const float v01 = __ldg(av + base + 3);
    const float v11 = __ldg(av + base + 4);
    return (1.f - f0) * ((1.f - f1) * v00 + f1 * v01)
         +        f0  * ((1.f - f1) * v10 + f1 * v11);
}

template<int LAST, int FIRST>
__global__ void __launch_bounds__(NTHREADS, 2)
gemm_act(const int8_t* __restrict__ A, const int8_t* __restrict__ B, int layer,
         const float* __restrict__ bias, const float* __restrict__ act,
         const float* __restrict__ scale_p, const float* __restrict__ out_bias,
         int8_t* __restrict__ Ynext, float* __restrict__ Yout)
{
    extern __shared__ __align__(1024) char smem[];
    const uint32_t sb = smem_u32(smem);
    const int tid  = threadIdx.x;
    const int wid  = tid >> 5;
    const int lane = tid & 31;
    const int rowBase = blockIdx.y * BM;
    const int nBase   = blockIdx.x * BN;
    const int warp_m = (wid & 1) * 64;        // {0, 64}
    const int warp_n = (wid >> 1) * 32;       // {0, 32, 64, 96}

    // ---- loader mapping: 256 thr; r0 = tid>>3 in 0..31, 16B segment ----
    const int r0   = tid >> 3;
    const int cseg = (tid & 7) * 16;
    const uint32_t swc = (uint32_t)cseg ^ ((uint32_t)(r0 & 7) * 16);
    uint32_t swOff[4];
    #pragma unroll
    for (int i = 0; i < 4; i++)
        swOff[i] = (uint32_t)(r0 + 32 * i) * 128 + swc;

    const char* gA = (const char*)(A + (size_t)(rowBase + r0) * INW) + cseg;
    const char* gB = (const char*)(B + (size_t)(nBase  + r0) * INW) + cseg;
    const size_t RSTRIDE = (size_t)32 * INW;   // 32 rows (1 byte/elem)

    int acc[4][4][4];
    #pragma unroll
    for (int a = 0; a < 4; a++)
        #pragma unroll
        for (int b = 0; b < 4; b++)
            #pragma unroll
            for (int q = 0; q < 4; q++) acc[a][b][q] = 0;

    // prologue: stages 0..1
    #pragma unroll
    for (int p = 0; p < 2; p++) {
        const uint32_t st = sb + p * STAGE;
        const size_t go = (size_t)p * 128;   // BK bytes along k
        #pragma unroll
        for (int i = 0; i < 4; i++) {
            CP_ASYNC16(st + OFF_A + swOff[i], gA + go + i * RSTRIDE);
            CP_ASYNC16(st + OFF_B + swOff[i], gB + go + i * RSTRIDE);
        }
        CP_COMMIT();
    }

    for (int c = 0; c < NCHUNK; c++) {
        if (c + 1 < NCHUNK) CP_WAIT1();
        else                CP_WAIT0();
        __syncthreads();   // stage c resident; all warps done reading stage (c-1)%3

        if (c + 2 < NCHUNK) {
            const uint32_t st = sb + ((c + 2) % NSTAGE) * STAGE;
            const size_t go = (size_t)(c + 2) * 128;
            #pragma unroll
            for (int i = 0; i < 4; i++) {
                CP_ASYNC16(st + OFF_A + swOff[i], gA + go + i * RSTRIDE);
                CP_ASYNC16(st + OFF_B + swOff[i], gB + go + i * RSTRIDE);
            }
            CP_COMMIT();
        }
        const uint32_t st = sb + (c % NSTAGE) * STAGE;
        compute_stage(st + OFF_A, st + OFF_B, lane, warp_m, warp_n, acc);
    }

    // ---- epilogue: dequant + bias + grid activation ----
    const float ls = cbrtf(fabsf(scale_p[0]));
    const float wmax = fmaxf(__uint_as_float(g_umax[layer]), 1e-20f);
    const float aScale = FIRST ? (fmaxf(__uint_as_float(g_umax[3]), 1e-20f) * ls) : ls;
    const float dq = (aScale / 127.f) * (wmax / 127.f);
    const int gWarp = ((nBase + warp_n) >> 1);
    const int glWarp = (warp_n >> 1);   // CTA-local group offset (0,16,32,48)

    #pragma unroll
    for (int mb = 0; mb < 4; mb++) {
        const int rl  = warp_m + mb * 16 + (lane >> 2);   // CTA-local row
        const int rlo = rowBase + rl;
        #pragma unroll
        for (int nb = 0; nb < 4; nb++) {
            const int g  = gWarp + nb * 4 + (lane & 3);
            const int c0 = 2 * g;
            const float b0v = bias[c0], b1v = bias[c0 + 1];
            const float* av = act + (size_t)g * 9;
            const int* d = acc[mb][nb];
            const float oLo = act_eval((float)d[0] * dq + b0v, (float)d[1] * dq + b1v, av);
            const float oHi = act_eval((float)d[2] * dq + b0v, (float)d[3] * dq + b1v, av);
            if (LAST) {
                const float ob = out_bias[g];
                Yout[(size_t)rlo * NG + g]       = oLo + ob;
                Yout[(size_t)(rlo + 8) * NG + g] = oHi + ob;
            } else {
                // stage int8 result in SMEM (stage-0 buffer is dead past the last sync)
                const int gl = glWarp + nb * 4 + (lane & 3);
                smem[rl * STG_STRIDE + gl]       = (char)(int8_t)q8(oLo, 127.f);
                smem[(rl + 8) * STG_STRIDE + gl] = (char)(int8_t)q8(oHi, 127.f);
            }
        }
    }
    if (!LAST) {
        __syncthreads();
        // coalesced copy-out: 128 rows x 64 bytes; thread -> 32B of one row
        const int r = tid >> 1, half = tid & 1;
        const char* src = smem + r * STG_STRIDE + half * 32;
        uint4 v0 = *(const uint4*)src;
        uint4 v1 = *(const uint4*)(src + 16);
        int8_t* dst = Ynext + (size_t)(rowBase + r) * NG + (nBase >> 1) + half * 32;
        *(uint4*)dst        = v0;
        *(uint4*)(dst + 16) = v1;
    }
}

extern "C" void kernel_launch(void* const* d_in, const int* in_sizes, int n_in,
                              void* d_out, int out_size)
{
    (void)in_sizes; (void)n_in; (void)out_size;
    const float* X     = (const float*)d_in[0];
    const float* w0    = (const float*)d_in[1];
    const float* b0    = (const float*)d_in[2];
    const float* a0    = (const float*)d_in[3];
    const float* w1    = (const float*)d_in[4];
    const float* b1    = (const float*)d_in[5];
    const float* a1    = (const float*)d_in[6];
    const float* w2    = (const float*)d_in[7];
    const float* b2    = (const float*)d_in[8];
    const float* a2    = (const float*)d_in[9];
    const float* scale = (const float*)d_in[10];
    const float* outb  = (const float*)d_in[11];
    float* out = (float*)d_out;

    int8_t *A0, *A1, *B;
    cudaGetSymbolAddress((void**)&A0, g_A0);
    cudaGetSymbolAddress((void**)&A1, g_A1);
    cudaGetSymbolAddress((void**)&B,  g_B);
    const size_t WSTRIDE = (size_t)OUTW * INW;

    cudaFuncSetAttribute(gemm_act<0,1>, cudaFuncAttributeMaxDynamicSharedMemorySize, SMEM_TOTAL);
    cudaFuncSetAttribute(gemm_act<0,0>, cudaFuncAttributeMaxDynamicSharedMemorySize, SMEM_TOTAL);
    cudaFuncSetAttribute(gemm_act<1,0>, cudaFuncAttributeMaxDynamicSharedMemorySize, SMEM_TOTAL);

    // scales
    reset_umax<<<1, 32>>>();
    absmax_x<<<1024, 256>>>(X);
    absmax_w3<<<dim3(256, 3), 256>>>(w0, w1, w2);

    // quantize
    prep_x<<<(NROWS * INW) / (256 * 16), 256>>>(X, A0);
    prep_w3<<<dim3(INW / 32, OUTW / 128, 3), 256>>>(w0, w1, w2, B);

    dim3 ggrid(OUTW / BN, NROWS / BM);   // (16, 128)
    gemm_act<0,1><<<ggrid, NTHREADS, SMEM_TOTAL>>>(A0, B + 0 * WSTRIDE, 0,
                                                   b0, a0, scale, nullptr, A1, nullptr);
    gemm_act<0,0><<<ggrid, NTHREADS, SMEM_TOTAL>>>(A1, B + 1 * WSTRIDE, 1,
                                                   b1, a1, scale, nullptr, A0, nullptr);
    gemm_act<1,0><<<ggrid, NTHREADS, SMEM_TOTAL>>>(A0, B + 2 * WSTRIDE, 2,
                                                   b2, a2, scale, outb, nullptr, out);
}